// round 4
// baseline (speedup 1.0000x reference)
#include <cuda_runtime.h>
#include <math.h>

#define TOK   4096
#define FDIM  1024
#define NHEAD 16
#define DHEAD 64
#define MLPD  4096
#define NSEQ  2048

// ---------------------------------------------------------------------------
// Scratch (device globals: allocation-free per harness rules)
// ---------------------------------------------------------------------------
__device__ float g_h   [TOK * FDIM];   // LN1 output
__device__ float g_q   [TOK * FDIM];   // [b][h][n][dh]
__device__ float g_k   [TOK * FDIM];   // [b][h][n][dh]
__device__ float g_v   [TOK * FDIM];   // [b][h][n][dh]
__device__ float g_attn[TOK * FDIM];   // [token][f]
__device__ float g_out [TOK * FDIM];   // residual-1 output
__device__ float g_h2  [TOK * FDIM];   // LN2 output
__device__ float g_m1  [TOK * MLPD];   // MLP hidden

__device__ __forceinline__ float gelu_exact(float x) {
    return 0.5f * x * (1.0f + erff(x * 0.70710678118654752f));
}

// ---------------------------------------------------------------------------
// LayerNorm: one block per row (1024 floats), 256 threads, 1 float4 each
// ---------------------------------------------------------------------------
__global__ void __launch_bounds__(256) ln_kernel(const float* __restrict__ x,
                                                 const float* __restrict__ g,
                                                 const float* __restrict__ b,
                                                 float* __restrict__ out) {
    int row = blockIdx.x;
    const float4* xr = reinterpret_cast<const float4*>(x + (size_t)row * FDIM);
    float4 v = xr[threadIdx.x];

    float s  = v.x + v.y + v.z + v.w;
    float s2 = v.x * v.x + v.y * v.y + v.z * v.z + v.w * v.w;

    #pragma unroll
    for (int o = 16; o > 0; o >>= 1) {
        s  += __shfl_xor_sync(0xffffffffu, s,  o);
        s2 += __shfl_xor_sync(0xffffffffu, s2, o);
    }
    __shared__ float ss[8], ss2[8];
    int w = threadIdx.x >> 5, lane = threadIdx.x & 31;
    if (lane == 0) { ss[w] = s; ss2[w] = s2; }
    __syncthreads();
    s = 0.f; s2 = 0.f;
    #pragma unroll
    for (int i = 0; i < 8; i++) { s += ss[i]; s2 += ss2[i]; }

    float mu  = s * (1.0f / FDIM);
    float var = s2 * (1.0f / FDIM) - mu * mu;
    float r   = rsqrtf(var + 1e-5f);

    float4 gg = reinterpret_cast<const float4*>(g)[threadIdx.x];
    float4 bb = reinterpret_cast<const float4*>(b)[threadIdx.x];
    float4 o4;
    o4.x = (v.x - mu) * r * gg.x + bb.x;
    o4.y = (v.y - mu) * r * gg.y + bb.y;
    o4.z = (v.z - mu) * r * gg.z + bb.z;
    o4.w = (v.w - mu) * r * gg.w + bb.w;
    reinterpret_cast<float4*>(out + (size_t)row * FDIM)[threadIdx.x] = o4;
}

// ---------------------------------------------------------------------------
// SGEMM: C[M,N] = A[M,K] @ B[K,N] + bias, fused epilogue.
//   GELU: exact gelu after bias
//   RES : += res[row*N+col] (after gelu if both)
//   QKV : scatter to [b][h][n][dh] layout instead of row-major
// BM=BN=128, BK=16, 256 threads, 8x8 microtile per thread.
// M,N multiples of 128; K multiple of 16.
// ---------------------------------------------------------------------------
template <bool GELU, bool RES, bool QKV>
__global__ void __launch_bounds__(256) sgemm_kernel(
    const float* __restrict__ A, const float* __restrict__ B,
    const float* __restrict__ bias, const float* __restrict__ res,
    float* __restrict__ C, int M, int N, int K)
{
    __shared__ float As[16][128];
    __shared__ float Bs[16][128];

    const int tid = threadIdx.x;
    const int tx = tid & 15;       // 0..15 (N dir)
    const int ty = tid >> 4;       // 0..15 (M dir)

    const float* Ab = A + (size_t)blockIdx.y * 128 * K;
    const float* Bb = B + blockIdx.x * 128;

    float acc[8][8];
    #pragma unroll
    for (int i = 0; i < 8; i++)
        #pragma unroll
        for (int j = 0; j < 8; j++) acc[i][j] = 0.f;

    for (int k0 = 0; k0 < K; k0 += 16) {
        // Load A tile (128x16), store transposed
        #pragma unroll
        for (int t = 0; t < 2; t++) {
            int idx = tid + t * 256;          // 0..511
            int r   = idx >> 2;               // 0..127
            int c4  = idx & 3;                // 0..3
            float4 av = *reinterpret_cast<const float4*>(Ab + (size_t)r * K + k0 + c4 * 4);
            As[c4 * 4 + 0][r] = av.x;
            As[c4 * 4 + 1][r] = av.y;
            As[c4 * 4 + 2][r] = av.z;
            As[c4 * 4 + 3][r] = av.w;
        }
        // Load B tile (16x128)
        #pragma unroll
        for (int t = 0; t < 2; t++) {
            int idx = tid + t * 256;
            int r   = idx >> 5;               // 0..15
            int c4  = idx & 31;               // 0..31
            *reinterpret_cast<float4*>(&Bs[r][c4 * 4]) =
                *reinterpret_cast<const float4*>(Bb + (size_t)(k0 + r) * N + c4 * 4);
        }
        __syncthreads();

        #pragma unroll
        for (int kk = 0; kk < 16; kk++) {
            float a[8], bb[8];
            *reinterpret_cast<float4*>(&a[0])  = *reinterpret_cast<float4*>(&As[kk][ty * 8]);
            *reinterpret_cast<float4*>(&a[4])  = *reinterpret_cast<float4*>(&As[kk][ty * 8 + 4]);
            *reinterpret_cast<float4*>(&bb[0]) = *reinterpret_cast<float4*>(&Bs[kk][tx * 8]);
            *reinterpret_cast<float4*>(&bb[4]) = *reinterpret_cast<float4*>(&Bs[kk][tx * 8 + 4]);
            #pragma unroll
            for (int i = 0; i < 8; i++)
                #pragma unroll
                for (int j = 0; j < 8; j++)
                    acc[i][j] += a[i] * bb[j];
        }
        __syncthreads();
    }

    // Epilogue
    #pragma unroll
    for (int i = 0; i < 8; i++) {
        int row = blockIdx.y * 128 + ty * 8 + i;
        #pragma unroll
        for (int j = 0; j < 8; j++) {
            int col = blockIdx.x * 128 + tx * 8 + j;
            float v = acc[i][j] + bias[col];
            if (GELU) v = gelu_exact(v);
            if (RES)  v += res[(size_t)row * N + col];
            if (QKV) {
                int b = row >> 11;        // /2048
                int n = row & 2047;
                int h = col >> 6;         // /64
                int d = col & 63;
                C[((size_t)((b * NHEAD + h) * NSEQ + n)) * DHEAD + d] = v;
            } else {
                C[(size_t)row * N + col] = v;
            }
        }
    }
}

// ---------------------------------------------------------------------------
// Flash attention with off-by-one softmax + per-head slimming.
// q/k/v layout: [b][h][n][dh].  out layout: [token][FDIM].
// Grid: (B*H, NSEQ/128), 128 threads, 1 query row / thread.
// ---------------------------------------------------------------------------
__global__ void __launch_bounds__(128) attn_kernel(
    const float* __restrict__ q, const float* __restrict__ k,
    const float* __restrict__ v, const float* __restrict__ slim,
    float* __restrict__ out)
{
    __shared__ float4 Ks[64 * 16];   // 64 keys x 64 dh
    __shared__ float4 Vs[64 * 16];

    const int bh = blockIdx.x;               // 0..31
    const int b  = bh >> 4;
    const int h  = bh & 15;
    const int qi = blockIdx.y * 128 + threadIdx.x;   // 0..2047

    const float4* qrow = reinterpret_cast<const float4*>(
        q + ((size_t)bh * NSEQ + qi) * DHEAD);

    float4 q4[16];
    #pragma unroll
    for (int i = 0; i < 16; i++) {
        float4 t = qrow[i];
        // fold 1/sqrt(DH)=1/8 into q
        t.x *= 0.125f; t.y *= 0.125f; t.z *= 0.125f; t.w *= 0.125f;
        q4[i] = t;
    }

    float4 o4[16];
    #pragma unroll
    for (int i = 0; i < 16; i++) o4[i] = make_float4(0.f, 0.f, 0.f, 0.f);
    float m = -1e30f, l = 0.f;

    const float4* kb = reinterpret_cast<const float4*>(k + (size_t)bh * NSEQ * DHEAD);
    const float4* vb = reinterpret_cast<const float4*>(v + (size_t)bh * NSEQ * DHEAD);

    for (int kb0 = 0; kb0 < NSEQ; kb0 += 64) {
        __syncthreads();
        #pragma unroll
        for (int i = 0; i < 8; i++) {
            int idx = threadIdx.x + i * 128;       // 0..1023 float4s
            Ks[idx] = kb[kb0 * 16 + idx];
            Vs[idx] = vb[kb0 * 16 + idx];
        }
        __syncthreads();

        for (int j = 0; j < 64; j++) {
            const float4* kr = &Ks[j * 16];
            float sx = 0.f, sy = 0.f, sz = 0.f, sw = 0.f;
            #pragma unroll
            for (int d = 0; d < 16; d++) {
                float4 kk = kr[d];
                sx += q4[d].x * kk.x;
                sy += q4[d].y * kk.y;
                sz += q4[d].z * kk.z;
                sw += q4[d].w * kk.w;
            }
            float s = (sx + sy) + (sz + sw);

            if (s > m) {                      // rare (~log(n) times per row)
                float scale = expf(m - s);
                #pragma unroll
                for (int d = 0; d < 16; d++) {
                    o4[d].x *= scale; o4[d].y *= scale;
                    o4[d].z *= scale; o4[d].w *= scale;
                }
                l *= scale;
                m = s;
            }
            float p = expf(s - m);
            l += p;
            const float4* vr = &Vs[j * 16];
            #pragma unroll
            for (int d = 0; d < 16; d++) {
                float4 vv = vr[d];
                o4[d].x += p * vv.x; o4[d].y += p * vv.y;
                o4[d].z += p * vv.z; o4[d].w += p * vv.w;
            }
        }
    }

    // off-by-one softmax denominator: 1 + sum(exp(a - max)); slim after softmax
    float inv = slim[h] / (1.0f + l);
    float4* orow = reinterpret_cast<float4*>(
        out + ((size_t)(b * NSEQ + qi)) * FDIM + h * DHEAD);
    #pragma unroll
    for (int d = 0; d < 16; d++) {
        float4 ov;
        ov.x = o4[d].x * inv; ov.y = o4[d].y * inv;
        ov.z = o4[d].z * inv; ov.w = o4[d].w * inv;
        orow[d] = ov;
    }
}

// ---------------------------------------------------------------------------
// Launch
// ---------------------------------------------------------------------------
extern "C" void kernel_launch(void* const* d_in, const int* in_sizes, int n_in,
                              void* d_out, int out_size)
{
    const float* x    = (const float*)d_in[0];
    const float* ln1g = (const float*)d_in[1];
    const float* ln1b = (const float*)d_in[2];
    const float* Wq   = (const float*)d_in[3];
    const float* bq   = (const float*)d_in[4];
    const float* Wk   = (const float*)d_in[5];
    const float* bk   = (const float*)d_in[6];
    const float* Wv   = (const float*)d_in[7];
    const float* bv   = (const float*)d_in[8];
    const float* Wo   = (const float*)d_in[9];
    const float* bo   = (const float*)d_in[10];
    const float* slim = (const float*)d_in[11];
    const float* ln2g = (const float*)d_in[12];
    const float* ln2b = (const float*)d_in[13];
    const float* W1   = (const float*)d_in[14];
    const float* b1   = (const float*)d_in[15];
    const float* W2   = (const float*)d_in[16];
    const float* b2   = (const float*)d_in[17];
    float* out = (float*)d_out;

    float *ph, *pq, *pk, *pv, *pa, *po, *ph2, *pm1;
    cudaGetSymbolAddress((void**)&ph,  g_h);
    cudaGetSymbolAddress((void**)&pq,  g_q);
    cudaGetSymbolAddress((void**)&pk,  g_k);
    cudaGetSymbolAddress((void**)&pv,  g_v);
    cudaGetSymbolAddress((void**)&pa,  g_attn);
    cudaGetSymbolAddress((void**)&po,  g_out);
    cudaGetSymbolAddress((void**)&ph2, g_h2);
    cudaGetSymbolAddress((void**)&pm1, g_m1);

    dim3 gF(FDIM / 128, TOK / 128);   // (8, 32)
    dim3 gM(MLPD / 128, TOK / 128);   // (32, 32)

    // 1. LN1
    ln_kernel<<<TOK, 256>>>(x, ln1g, ln1b, ph);

    // 2. Q/K/V projections (scatter into [b,h,n,d])
    sgemm_kernel<false, false, true><<<gF, 256>>>(ph, Wq, bq, nullptr, pq, TOK, FDIM, FDIM);
    sgemm_kernel<false, false, true><<<gF, 256>>>(ph, Wk, bk, nullptr, pk, TOK, FDIM, FDIM);
    sgemm_kernel<false, false, true><<<gF, 256>>>(ph, Wv, bv, nullptr, pv, TOK, FDIM, FDIM);

    // 3. Attention (off-by-one softmax + slim)
    attn_kernel<<<dim3(2 * NHEAD, NSEQ / 128), 128>>>(pq, pk, pv, slim, pa);

    // 4. Output projection + residual 1
    sgemm_kernel<false, true, false><<<gF, 256>>>(pa, Wo, bo, x, po, TOK, FDIM, FDIM);

    // 5. LN2
    ln_kernel<<<TOK, 256>>>(po, ln2g, ln2b, ph2);

    // 6. MLP up + GELU
    sgemm_kernel<true, false, false><<<gM, 256>>>(ph2, W1, b1, nullptr, pm1, TOK, MLPD, FDIM);

    // 7. MLP down + GELU + residual 2 -> final output
    sgemm_kernel<true, true, false><<<gF, 256>>>(pm1, W2, b2, po, out, TOK, FDIM, MLPD);
}

// round 5
// speedup vs baseline: 2.2639x; 2.2639x over previous
#include <cuda_runtime.h>
#include <math.h>
#include <stdint.h>

#define TOK   4096
#define FDIM  1024
#define NHEAD 16
#define DHEAD 64
#define MLPD  4096
#define NSEQ  2048

// ---------------------------------------------------------------------------
// Scratch (device globals: allocation-free per harness rules)
// ---------------------------------------------------------------------------
__device__ float g_h   [TOK * FDIM];   // LN1 output
__device__ float g_q   [TOK * FDIM];   // [b][h][n][dh]
__device__ float g_k   [TOK * FDIM];   // [b][h][n][dh]
__device__ float g_v   [TOK * FDIM];   // [b][h][n][dh]
__device__ float g_attn[TOK * FDIM];   // [token][f]
__device__ float g_out [TOK * FDIM];   // residual-1 output
__device__ float g_h2  [TOK * FDIM];   // LN2 output
__device__ float g_m1  [TOK * MLPD];   // MLP hidden

__device__ __forceinline__ float gelu_exact(float x) {
    return 0.5f * x * (1.0f + erff(x * 0.70710678118654752f));
}

__device__ __forceinline__ uint32_t f2tf32(float x) {
    uint32_t r;
    asm("cvt.rna.tf32.f32 %0, %1;" : "=r"(r) : "f"(x));
    return r;
}

__device__ __forceinline__ void mma_tf32(float c[4],
                                         uint32_t a0, uint32_t a1, uint32_t a2, uint32_t a3,
                                         uint32_t b0, uint32_t b1) {
    asm volatile(
        "mma.sync.aligned.m16n8k8.row.col.f32.tf32.tf32.f32 "
        "{%0,%1,%2,%3}, {%4,%5,%6,%7}, {%8,%9}, {%0,%1,%2,%3};"
        : "+f"(c[0]), "+f"(c[1]), "+f"(c[2]), "+f"(c[3])
        : "r"(a0), "r"(a1), "r"(a2), "r"(a3), "r"(b0), "r"(b1));
}

// ---------------------------------------------------------------------------
// LayerNorm: one block per row (1024 floats), 256 threads, 1 float4 each
// ---------------------------------------------------------------------------
__global__ void __launch_bounds__(256) ln_kernel(const float* __restrict__ x,
                                                 const float* __restrict__ g,
                                                 const float* __restrict__ b,
                                                 float* __restrict__ out) {
    int row = blockIdx.x;
    const float4* xr = reinterpret_cast<const float4*>(x + (size_t)row * FDIM);
    float4 v = xr[threadIdx.x];

    float s  = v.x + v.y + v.z + v.w;
    float s2 = v.x * v.x + v.y * v.y + v.z * v.z + v.w * v.w;

    #pragma unroll
    for (int o = 16; o > 0; o >>= 1) {
        s  += __shfl_xor_sync(0xffffffffu, s,  o);
        s2 += __shfl_xor_sync(0xffffffffu, s2, o);
    }
    __shared__ float ss[8], ss2[8];
    int w = threadIdx.x >> 5, lane = threadIdx.x & 31;
    if (lane == 0) { ss[w] = s; ss2[w] = s2; }
    __syncthreads();
    s = 0.f; s2 = 0.f;
    #pragma unroll
    for (int i = 0; i < 8; i++) { s += ss[i]; s2 += ss2[i]; }

    float mu  = s * (1.0f / FDIM);
    float var = s2 * (1.0f / FDIM) - mu * mu;
    float r   = rsqrtf(var + 1e-5f);

    float4 gg = reinterpret_cast<const float4*>(g)[threadIdx.x];
    float4 bb = reinterpret_cast<const float4*>(b)[threadIdx.x];
    float4 o4;
    o4.x = (v.x - mu) * r * gg.x + bb.x;
    o4.y = (v.y - mu) * r * gg.y + bb.y;
    o4.z = (v.z - mu) * r * gg.z + bb.z;
    o4.w = (v.w - mu) * r * gg.w + bb.w;
    reinterpret_cast<float4*>(out + (size_t)row * FDIM)[threadIdx.x] = o4;
}

// ---------------------------------------------------------------------------
// TF32 tensor-core GEMM: C[M,N] = A[M,K] @ B[K,N] + bias, fused epilogue.
//   GELU: exact gelu after bias
//   RES : += res (after gelu if both)
//   QKV : scatter to [b][h][n][dh] layout
// BM=BN=128, BK=32, 256 threads = 8 warps (2 m x 4 n), warp tile 64x32.
// mma.sync.m16n8k8 tf32, fp32 accumulate. M,N mult of 128; K mult of 32.
// ---------------------------------------------------------------------------
#define AS_STRIDE 132
#define BS_STRIDE 132

template <bool GELU, bool RES, bool QKV>
__global__ void __launch_bounds__(256) sgemm_tf32(
    const float* __restrict__ A, const float* __restrict__ B,
    const float* __restrict__ bias, const float* __restrict__ res,
    float* __restrict__ C, int M, int N, int K)
{
    __shared__ uint32_t As[32 * AS_STRIDE];   // [k][m], tf32 bits
    __shared__ uint32_t Bs[32 * BS_STRIDE];   // [k][n], tf32 bits

    const int tid    = threadIdx.x;
    const int warp   = tid >> 5;
    const int lane   = tid & 31;
    const int g      = lane >> 2;      // 0..7
    const int tig    = lane & 3;       // 0..3
    const int warp_m = (warp & 1) * 64;
    const int warp_n = (warp >> 1) * 32;

    const float* Ab = A + (size_t)blockIdx.y * 128 * K;
    const float* Bb = B + blockIdx.x * 128;

    float acc[4][4][4];
    #pragma unroll
    for (int mt = 0; mt < 4; mt++)
        #pragma unroll
        for (int nt = 0; nt < 4; nt++)
            #pragma unroll
            for (int r = 0; r < 4; r++) acc[mt][nt][r] = 0.f;

    for (int k0 = 0; k0 < K; k0 += 32) {
        // --- A tile: 128 rows x 32 k, store transposed [k][m] as tf32 ---
        #pragma unroll
        for (int t = 0; t < 4; t++) {
            int idx = tid + t * 256;            // 0..1023
            int r   = idx >> 3;                 // 0..127
            int c4  = idx & 7;                  // 0..7
            float4 av = *reinterpret_cast<const float4*>(Ab + (size_t)r * K + k0 + c4 * 4);
            As[(c4 * 4 + 0) * AS_STRIDE + r] = f2tf32(av.x);
            As[(c4 * 4 + 1) * AS_STRIDE + r] = f2tf32(av.y);
            As[(c4 * 4 + 2) * AS_STRIDE + r] = f2tf32(av.z);
            As[(c4 * 4 + 3) * AS_STRIDE + r] = f2tf32(av.w);
        }
        // --- B tile: 32 k x 128 cols, [k][n] as tf32, vector stores ---
        #pragma unroll
        for (int t = 0; t < 4; t++) {
            int idx = tid + t * 256;
            int r   = idx >> 5;                 // 0..31
            int c4  = idx & 31;                 // 0..31
            float4 bv = *reinterpret_cast<const float4*>(Bb + (size_t)(k0 + r) * N + c4 * 4);
            uint4 bu;
            bu.x = f2tf32(bv.x); bu.y = f2tf32(bv.y);
            bu.z = f2tf32(bv.z); bu.w = f2tf32(bv.w);
            *reinterpret_cast<uint4*>(&Bs[r * BS_STRIDE + c4 * 4]) = bu;
        }
        __syncthreads();

        #pragma unroll
        for (int ks = 0; ks < 4; ks++) {
            const int kk = ks * 8;
            uint32_t af[4][4], bf[4][2];
            #pragma unroll
            for (int mt = 0; mt < 4; mt++) {
                int mrow = warp_m + mt * 16 + g;
                af[mt][0] = As[(kk + tig)     * AS_STRIDE + mrow];
                af[mt][1] = As[(kk + tig)     * AS_STRIDE + mrow + 8];
                af[mt][2] = As[(kk + tig + 4) * AS_STRIDE + mrow];
                af[mt][3] = As[(kk + tig + 4) * AS_STRIDE + mrow + 8];
            }
            #pragma unroll
            for (int nt = 0; nt < 4; nt++) {
                int ncol = warp_n + nt * 8 + g;
                bf[nt][0] = Bs[(kk + tig)     * BS_STRIDE + ncol];
                bf[nt][1] = Bs[(kk + tig + 4) * BS_STRIDE + ncol];
            }
            #pragma unroll
            for (int mt = 0; mt < 4; mt++)
                #pragma unroll
                for (int nt = 0; nt < 4; nt++)
                    mma_tf32(acc[mt][nt], af[mt][0], af[mt][1], af[mt][2], af[mt][3],
                             bf[nt][0], bf[nt][1]);
        }
        __syncthreads();
    }

    // --- Epilogue: c0,c1 -> (row g, cols 2*tig,2*tig+1); c2,c3 -> row g+8 ---
    const int rowbase = blockIdx.y * 128 + warp_m;
    const int colbase = blockIdx.x * 128 + warp_n;

    #pragma unroll
    for (int mt = 0; mt < 4; mt++) {
        #pragma unroll
        for (int nt = 0; nt < 4; nt++) {
            int c = colbase + nt * 8 + tig * 2;
            float bx = bias[c], by = bias[c + 1];
            #pragma unroll
            for (int half = 0; half < 2; half++) {
                int r = rowbase + mt * 16 + g + half * 8;
                float v0 = acc[mt][nt][half * 2 + 0] + bx;
                float v1 = acc[mt][nt][half * 2 + 1] + by;
                if (GELU) { v0 = gelu_exact(v0); v1 = gelu_exact(v1); }
                if (RES) {
                    float2 rr = *reinterpret_cast<const float2*>(res + (size_t)r * N + c);
                    v0 += rr.x; v1 += rr.y;
                }
                float2 ov = make_float2(v0, v1);
                if (QKV) {
                    int b = r >> 11;
                    int n = r & 2047;
                    int h = c >> 6;
                    int d = c & 63;
                    *reinterpret_cast<float2*>(
                        C + ((size_t)((b * NHEAD + h) * NSEQ + n)) * DHEAD + d) = ov;
                } else {
                    *reinterpret_cast<float2*>(C + (size_t)r * N + c) = ov;
                }
            }
        }
    }
}

// ---------------------------------------------------------------------------
// Flash attention with off-by-one softmax + per-head slimming.
// q/k/v layout: [b][h][n][dh].  out layout: [token][FDIM].
// Grid: (B*H, NSEQ/128), 128 threads, 1 query row / thread.
// ---------------------------------------------------------------------------
__global__ void __launch_bounds__(128) attn_kernel(
    const float* __restrict__ q, const float* __restrict__ k,
    const float* __restrict__ v, const float* __restrict__ slim,
    float* __restrict__ out)
{
    __shared__ float4 Ks[64 * 16];   // 64 keys x 64 dh
    __shared__ float4 Vs[64 * 16];

    const int bh = blockIdx.x;               // 0..31
    const int b  = bh >> 4;
    const int h  = bh & 15;
    const int qi = blockIdx.y * 128 + threadIdx.x;   // 0..2047

    const float4* qrow = reinterpret_cast<const float4*>(
        q + ((size_t)bh * NSEQ + qi) * DHEAD);

    float4 q4[16];
    #pragma unroll
    for (int i = 0; i < 16; i++) {
        float4 t = qrow[i];
        t.x *= 0.125f; t.y *= 0.125f; t.z *= 0.125f; t.w *= 0.125f;  // 1/sqrt(DH)
        q4[i] = t;
    }

    float4 o4[16];
    #pragma unroll
    for (int i = 0; i < 16; i++) o4[i] = make_float4(0.f, 0.f, 0.f, 0.f);
    float m = -1e30f, l = 0.f;

    const float4* kb = reinterpret_cast<const float4*>(k + (size_t)bh * NSEQ * DHEAD);
    const float4* vb = reinterpret_cast<const float4*>(v + (size_t)bh * NSEQ * DHEAD);

    for (int kb0 = 0; kb0 < NSEQ; kb0 += 64) {
        __syncthreads();
        #pragma unroll
        for (int i = 0; i < 8; i++) {
            int idx = threadIdx.x + i * 128;       // 0..1023 float4s
            Ks[idx] = kb[kb0 * 16 + idx];
            Vs[idx] = vb[kb0 * 16 + idx];
        }
        __syncthreads();

        for (int j = 0; j < 64; j++) {
            const float4* kr = &Ks[j * 16];
            float sx = 0.f, sy = 0.f, sz = 0.f, sw = 0.f;
            #pragma unroll
            for (int d = 0; d < 16; d++) {
                float4 kk = kr[d];
                sx += q4[d].x * kk.x;
                sy += q4[d].y * kk.y;
                sz += q4[d].z * kk.z;
                sw += q4[d].w * kk.w;
            }
            float s = (sx + sy) + (sz + sw);

            if (s > m) {                      // rare (~log(n) times per row)
                float scale = __expf(m - s);
                #pragma unroll
                for (int d = 0; d < 16; d++) {
                    o4[d].x *= scale; o4[d].y *= scale;
                    o4[d].z *= scale; o4[d].w *= scale;
                }
                l *= scale;
                m = s;
            }
            float p = __expf(s - m);
            l += p;
            const float4* vr = &Vs[j * 16];
            #pragma unroll
            for (int d = 0; d < 16; d++) {
                float4 vv = vr[d];
                o4[d].x += p * vv.x; o4[d].y += p * vv.y;
                o4[d].z += p * vv.z; o4[d].w += p * vv.w;
            }
        }
    }

    // off-by-one softmax denominator: 1 + sum(exp(a - max)); slim after softmax
    float inv = slim[h] / (1.0f + l);
    float4* orow = reinterpret_cast<float4*>(
        out + ((size_t)(b * NSEQ + qi)) * FDIM + h * DHEAD);
    #pragma unroll
    for (int d = 0; d < 16; d++) {
        float4 ov;
        ov.x = o4[d].x * inv; ov.y = o4[d].y * inv;
        ov.z = o4[d].z * inv; ov.w = o4[d].w * inv;
        orow[d] = ov;
    }
}

// ---------------------------------------------------------------------------
// Launch
// ---------------------------------------------------------------------------
extern "C" void kernel_launch(void* const* d_in, const int* in_sizes, int n_in,
                              void* d_out, int out_size)
{
    const float* x    = (const float*)d_in[0];
    const float* ln1g = (const float*)d_in[1];
    const float* ln1b = (const float*)d_in[2];
    const float* Wq   = (const float*)d_in[3];
    const float* bq   = (const float*)d_in[4];
    const float* Wk   = (const float*)d_in[5];
    const float* bk   = (const float*)d_in[6];
    const float* Wv   = (const float*)d_in[7];
    const float* bv   = (const float*)d_in[8];
    const float* Wo   = (const float*)d_in[9];
    const float* bo   = (const float*)d_in[10];
    const float* slim = (const float*)d_in[11];
    const float* ln2g = (const float*)d_in[12];
    const float* ln2b = (const float*)d_in[13];
    const float* W1   = (const float*)d_in[14];
    const float* b1   = (const float*)d_in[15];
    const float* W2   = (const float*)d_in[16];
    const float* b2   = (const float*)d_in[17];
    float* out = (float*)d_out;

    float *ph, *pq, *pk, *pv, *pa, *po, *ph2, *pm1;
    cudaGetSymbolAddress((void**)&ph,  g_h);
    cudaGetSymbolAddress((void**)&pq,  g_q);
    cudaGetSymbolAddress((void**)&pk,  g_k);
    cudaGetSymbolAddress((void**)&pv,  g_v);
    cudaGetSymbolAddress((void**)&pa,  g_attn);
    cudaGetSymbolAddress((void**)&po,  g_out);
    cudaGetSymbolAddress((void**)&ph2, g_h2);
    cudaGetSymbolAddress((void**)&pm1, g_m1);

    dim3 gF(FDIM / 128, TOK / 128);   // (8, 32)
    dim3 gM(MLPD / 128, TOK / 128);   // (32, 32)

    // 1. LN1
    ln_kernel<<<TOK, 256>>>(x, ln1g, ln1b, ph);

    // 2. Q/K/V projections (scatter into [b,h,n,d])
    sgemm_tf32<false, false, true><<<gF, 256>>>(ph, Wq, bq, nullptr, pq, TOK, FDIM, FDIM);
    sgemm_tf32<false, false, true><<<gF, 256>>>(ph, Wk, bk, nullptr, pk, TOK, FDIM, FDIM);
    sgemm_tf32<false, false, true><<<gF, 256>>>(ph, Wv, bv, nullptr, pv, TOK, FDIM, FDIM);

    // 3. Attention (off-by-one softmax + slim)
    attn_kernel<<<dim3(2 * NHEAD, NSEQ / 128), 128>>>(pq, pk, pv, slim, pa);

    // 4. Output projection + residual 1
    sgemm_tf32<false, true, false><<<gF, 256>>>(pa, Wo, bo, x, po, TOK, FDIM, FDIM);

    // 5. LN2
    ln_kernel<<<TOK, 256>>>(po, ln2g, ln2b, ph2);

    // 6. MLP up + GELU
    sgemm_tf32<true, false, false><<<gM, 256>>>(ph2, W1, b1, nullptr, pm1, TOK, MLPD, FDIM);

    // 7. MLP down + GELU + residual 2 -> final output
    sgemm_tf32<true, true, false><<<gF, 256>>>(pm1, W2, b2, po, out, TOK, FDIM, MLPD);
}

// round 7
// speedup vs baseline: 4.2371x; 1.8715x over previous
#include <cuda_runtime.h>
#include <math.h>
#include <stdint.h>

#define TOK   4096
#define FDIM  1024
#define NHEAD 16
#define DHEAD 64
#define MLPD  4096
#define NSEQ  2048

// ---------------------------------------------------------------------------
// Scratch (device globals: allocation-free per harness rules)
// ---------------------------------------------------------------------------
__device__ float g_h   [TOK * FDIM];   // LN1 output
__device__ float g_q   [TOK * FDIM];   // [b][h][n][dh]
__device__ float g_k   [TOK * FDIM];   // [b][h][n][dh]
__device__ float g_v   [TOK * FDIM];   // [b][h][n][dh]
__device__ float g_attn[TOK * FDIM];   // [token][f]
__device__ float g_out [TOK * FDIM];   // residual-1 output
__device__ float g_h2  [TOK * FDIM];   // LN2 output
__device__ float g_m1  [TOK * MLPD];   // MLP hidden

__device__ __forceinline__ float gelu_exact(float x) {
    return 0.5f * x * (1.0f + erff(x * 0.70710678118654752f));
}

__device__ __forceinline__ uint32_t f2tf32(float x) {
    uint32_t r;
    asm("cvt.rna.tf32.f32 %0, %1;" : "=r"(r) : "f"(x));
    return r;
}

__device__ __forceinline__ void mma_tf32(float c[4],
                                         uint32_t a0, uint32_t a1, uint32_t a2, uint32_t a3,
                                         uint32_t b0, uint32_t b1) {
    asm volatile(
        "mma.sync.aligned.m16n8k8.row.col.f32.tf32.tf32.f32 "
        "{%0,%1,%2,%3}, {%4,%5,%6,%7}, {%8,%9}, {%0,%1,%2,%3};"
        : "+f"(c[0]), "+f"(c[1]), "+f"(c[2]), "+f"(c[3])
        : "r"(a0), "r"(a1), "r"(a2), "r"(a3), "r"(b0), "r"(b1));
}

// ---------------------------------------------------------------------------
// LayerNorm: one block per row (1024 floats), 256 threads, 1 float4 each
// ---------------------------------------------------------------------------
__global__ void __launch_bounds__(256) ln_kernel(const float* __restrict__ x,
                                                 const float* __restrict__ g,
                                                 const float* __restrict__ b,
                                                 float* __restrict__ out) {
    int row = blockIdx.x;
    const float4* xr = reinterpret_cast<const float4*>(x + (size_t)row * FDIM);
    float4 v = xr[threadIdx.x];

    float s  = v.x + v.y + v.z + v.w;
    float s2 = v.x * v.x + v.y * v.y + v.z * v.z + v.w * v.w;

    #pragma unroll
    for (int o = 16; o > 0; o >>= 1) {
        s  += __shfl_xor_sync(0xffffffffu, s,  o);
        s2 += __shfl_xor_sync(0xffffffffu, s2, o);
    }
    __shared__ float ss[8], ss2[8];
    int w = threadIdx.x >> 5, lane = threadIdx.x & 31;
    if (lane == 0) { ss[w] = s; ss2[w] = s2; }
    __syncthreads();
    s = 0.f; s2 = 0.f;
    #pragma unroll
    for (int i = 0; i < 8; i++) { s += ss[i]; s2 += ss2[i]; }

    float mu  = s * (1.0f / FDIM);
    float var = s2 * (1.0f / FDIM) - mu * mu;
    float r   = rsqrtf(var + 1e-5f);

    float4 gg = reinterpret_cast<const float4*>(g)[threadIdx.x];
    float4 bb = reinterpret_cast<const float4*>(b)[threadIdx.x];
    float4 o4;
    o4.x = (v.x - mu) * r * gg.x + bb.x;
    o4.y = (v.y - mu) * r * gg.y + bb.y;
    o4.z = (v.z - mu) * r * gg.z + bb.z;
    o4.w = (v.w - mu) * r * gg.w + bb.w;
    reinterpret_cast<float4*>(out + (size_t)row * FDIM)[threadIdx.x] = o4;
}

// ---------------------------------------------------------------------------
// TF32 tensor-core GEMM, double-buffered (2-stage pipeline).
// C[M,N] = A[M,K] @ B[K,N] + bias, fused epilogue (GELU/RES/QKV-scatter).
// BM=BN=128, BK=32, 256 threads = 8 warps (2 m x 4 n), warp tile 64x32.
// Dynamic smem: 2 x (A 32x132 + B 32x132) tf32 words = 67584 B.
// ---------------------------------------------------------------------------
#define TS 132
#define TILE_WORDS (32 * TS)

template <bool GELU, bool RES, bool QKV>
__global__ void __launch_bounds__(256) sgemm_tf32(
    const float* __restrict__ A, const float* __restrict__ B,
    const float* __restrict__ bias, const float* __restrict__ res,
    float* __restrict__ C, int M, int N, int K)
{
    extern __shared__ uint32_t smem[];
    uint32_t* As = smem;                      // [2][32][132]
    uint32_t* Bs = smem + 2 * TILE_WORDS;     // [2][32][132]

    const int tid    = threadIdx.x;
    const int warp   = tid >> 5;
    const int lane   = tid & 31;
    const int g      = lane >> 2;      // 0..7
    const int tig    = lane & 3;       // 0..3
    const int warp_m = (warp & 1) * 64;
    const int warp_n = (warp >> 1) * 32;

    const float* Ab = A + (size_t)blockIdx.y * 128 * K;
    const float* Bb = B + blockIdx.x * 128;

    // per-thread tile-load coordinates
    const int ar = tid >> 3, ac = tid & 7;            // A: rows ar, ar+32.., k-col ac*4
    const int br = tid >> 5, bc = tid & 31;           // B: k-row br, br+8.., col bc*4

    float acc[4][4][4];
    #pragma unroll
    for (int mt = 0; mt < 4; mt++)
        #pragma unroll
        for (int nt = 0; nt < 4; nt++)
            #pragma unroll
            for (int r = 0; r < 4; r++) acc[mt][nt][r] = 0.f;

    const int nk = K >> 5;

    // ---- prologue: tile 0 into buffer 0 ----
    {
        #pragma unroll
        for (int t = 0; t < 4; t++) {
            int r = ar + t * 32;
            float4 av = *reinterpret_cast<const float4*>(Ab + (size_t)r * K + ac * 4);
            As[(ac * 4 + 0) * TS + r] = f2tf32(av.x);
            As[(ac * 4 + 1) * TS + r] = f2tf32(av.y);
            As[(ac * 4 + 2) * TS + r] = f2tf32(av.z);
            As[(ac * 4 + 3) * TS + r] = f2tf32(av.w);
        }
        #pragma unroll
        for (int t = 0; t < 4; t++) {
            int r = br + t * 8;
            float4 bv = *reinterpret_cast<const float4*>(Bb + (size_t)r * N + bc * 4);
            uint4 bu;
            bu.x = f2tf32(bv.x); bu.y = f2tf32(bv.y);
            bu.z = f2tf32(bv.z); bu.w = f2tf32(bv.w);
            *reinterpret_cast<uint4*>(&Bs[r * TS + bc * 4]) = bu;
        }
    }
    __syncthreads();

    for (int kt = 0; kt < nk; kt++) {
        const uint32_t* Ac = As + (kt & 1) * TILE_WORDS;
        const uint32_t* Bc = Bs + (kt & 1) * TILE_WORDS;
        uint32_t* An = As + ((kt + 1) & 1) * TILE_WORDS;
        uint32_t* Bn = Bs + ((kt + 1) & 1) * TILE_WORDS;

        // issue next tile's global loads first (latency hidden under mma)
        float4 av[4], bv[4];
        if (kt + 1 < nk) {
            int k0 = (kt + 1) << 5;
            #pragma unroll
            for (int t = 0; t < 4; t++)
                av[t] = *reinterpret_cast<const float4*>(Ab + (size_t)(ar + t * 32) * K + k0 + ac * 4);
            #pragma unroll
            for (int t = 0; t < 4; t++)
                bv[t] = *reinterpret_cast<const float4*>(Bb + (size_t)(k0 + br + t * 8) * N + bc * 4);
        }

        // ---- compute current tile ----
        #pragma unroll
        for (int ks = 0; ks < 4; ks++) {
            const int kk = ks * 8;
            uint32_t af[4][4], bf[4][2];
            #pragma unroll
            for (int mt = 0; mt < 4; mt++) {
                int mrow = warp_m + mt * 16 + g;
                af[mt][0] = Ac[(kk + tig)     * TS + mrow];
                af[mt][1] = Ac[(kk + tig)     * TS + mrow + 8];
                af[mt][2] = Ac[(kk + tig + 4) * TS + mrow];
                af[mt][3] = Ac[(kk + tig + 4) * TS + mrow + 8];
            }
            #pragma unroll
            for (int nt = 0; nt < 4; nt++) {
                int ncol = warp_n + nt * 8 + g;
                bf[nt][0] = Bc[(kk + tig)     * TS + ncol];
                bf[nt][1] = Bc[(kk + tig + 4) * TS + ncol];
            }
            #pragma unroll
            for (int mt = 0; mt < 4; mt++)
                #pragma unroll
                for (int nt = 0; nt < 4; nt++)
                    mma_tf32(acc[mt][nt], af[mt][0], af[mt][1], af[mt][2], af[mt][3],
                             bf[nt][0], bf[nt][1]);
        }

        // ---- stash next tile into the other buffer ----
        if (kt + 1 < nk) {
            #pragma unroll
            for (int t = 0; t < 4; t++) {
                int r = ar + t * 32;
                An[(ac * 4 + 0) * TS + r] = f2tf32(av[t].x);
                An[(ac * 4 + 1) * TS + r] = f2tf32(av[t].y);
                An[(ac * 4 + 2) * TS + r] = f2tf32(av[t].z);
                An[(ac * 4 + 3) * TS + r] = f2tf32(av[t].w);
            }
            #pragma unroll
            for (int t = 0; t < 4; t++) {
                int r = br + t * 8;
                uint4 bu;
                bu.x = f2tf32(bv[t].x); bu.y = f2tf32(bv[t].y);
                bu.z = f2tf32(bv[t].z); bu.w = f2tf32(bv[t].w);
                *reinterpret_cast<uint4*>(&Bn[r * TS + bc * 4]) = bu;
            }
        }
        __syncthreads();
    }

    // --- Epilogue ---
    const int rowbase = blockIdx.y * 128 + warp_m;
    const int colbase = blockIdx.x * 128 + warp_n;

    #pragma unroll
    for (int mt = 0; mt < 4; mt++) {
        #pragma unroll
        for (int nt = 0; nt < 4; nt++) {
            int c = colbase + nt * 8 + tig * 2;
            float bx = bias[c], by = bias[c + 1];
            #pragma unroll
            for (int half = 0; half < 2; half++) {
                int r = rowbase + mt * 16 + g + half * 8;
                float v0 = acc[mt][nt][half * 2 + 0] + bx;
                float v1 = acc[mt][nt][half * 2 + 1] + by;
                if (GELU) { v0 = gelu_exact(v0); v1 = gelu_exact(v1); }
                if (RES) {
                    float2 rr = *reinterpret_cast<const float2*>(res + (size_t)r * N + c);
                    v0 += rr.x; v1 += rr.y;
                }
                float2 ov = make_float2(v0, v1);
                if (QKV) {
                    int b = r >> 11;
                    int n = r & 2047;
                    int h = c >> 6;
                    int d = c & 63;
                    *reinterpret_cast<float2*>(
                        C + ((size_t)((b * NHEAD + h) * NSEQ + n)) * DHEAD + d) = ov;
                } else {
                    *reinterpret_cast<float2*>(C + (size_t)r * N + c) = ov;
                }
            }
        }
    }
}

// ---------------------------------------------------------------------------
// Tensor-core flash attention, off-by-one softmax + per-head slimming.
// q/k/v layout: [b][h][n][dh]. out: [token][FDIM].
// Block: 128 threads (4 warps); q-tile 64 rows (16/warp); k-tiles of 64 keys.
// S = Q K^T via tf32 mma; P rearranged C-frag -> A-frag via quad shuffles;
// O += P V via tf32 mma.  Smem: K/V tiles, 64x68 tf32 each (Q staged via Ks).
// ---------------------------------------------------------------------------
#define KS_S 68

__global__ void __launch_bounds__(128) attn_mma(
    const float* __restrict__ q, const float* __restrict__ k,
    const float* __restrict__ v, const float* __restrict__ slim,
    float* __restrict__ out)
{
    __shared__ uint32_t Ks[64 * KS_S];
    __shared__ uint32_t Vs[64 * KS_S];

    const int bh = blockIdx.x;          // 0..31
    const int b  = bh >> 4;
    const int h  = bh & 15;
    const int qbase = blockIdx.y * 64;

    const int tid  = threadIdx.x;
    const int w    = tid >> 5;
    const int lane = tid & 31;
    const int g    = lane >> 2;         // 0..7
    const int tig  = lane & 3;          // 0..3
    const bool odd = tig & 1;

    // ---- stage Q (scaled by 1/8, tf32) through Ks, extract A-fragments ----
    const float4* Qg = reinterpret_cast<const float4*>(
        q + ((size_t)bh * NSEQ + qbase) * DHEAD);
    #pragma unroll
    for (int i = 0; i < 8; i++) {
        int idx = tid + i * 128;        // 0..1023
        int r = idx >> 4, c4 = idx & 15;
        float4 t = Qg[r * 16 + c4];
        Ks[r * KS_S + c4 * 4 + 0] = f2tf32(t.x * 0.125f);
        Ks[r * KS_S + c4 * 4 + 1] = f2tf32(t.y * 0.125f);
        Ks[r * KS_S + c4 * 4 + 2] = f2tf32(t.z * 0.125f);
        Ks[r * KS_S + c4 * 4 + 3] = f2tf32(t.w * 0.125f);
    }
    __syncthreads();

    uint32_t qa[8][4];
    {
        int row0 = w * 16 + g;
        #pragma unroll
        for (int ks = 0; ks < 8; ks++) {
            qa[ks][0] = Ks[ row0      * KS_S + ks * 8 + tig];
            qa[ks][1] = Ks[(row0 + 8) * KS_S + ks * 8 + tig];
            qa[ks][2] = Ks[ row0      * KS_S + ks * 8 + tig + 4];
            qa[ks][3] = Ks[(row0 + 8) * KS_S + ks * 8 + tig + 4];
        }
    }

    float oacc[8][4];
    #pragma unroll
    for (int nt = 0; nt < 8; nt++)
        #pragma unroll
        for (int r = 0; r < 4; r++) oacc[nt][r] = 0.f;
    float m0 = -1e30f, m1 = -1e30f, l0 = 0.f, l1 = 0.f;

    const float4* Kg = reinterpret_cast<const float4*>(k + (size_t)bh * NSEQ * DHEAD);
    const float4* Vg = reinterpret_cast<const float4*>(v + (size_t)bh * NSEQ * DHEAD);

    for (int kt = 0; kt < NSEQ / 64; kt++) {
        __syncthreads();   // previous tile fully consumed (also guards Q frags, iter 0)
        #pragma unroll
        for (int i = 0; i < 8; i++) {
            int idx = tid + i * 128;
            int r = idx >> 4, c4 = idx & 15;
            float4 tk = Kg[(kt * 64 + r) * 16 + c4];
            Ks[r * KS_S + c4 * 4 + 0] = f2tf32(tk.x);
            Ks[r * KS_S + c4 * 4 + 1] = f2tf32(tk.y);
            Ks[r * KS_S + c4 * 4 + 2] = f2tf32(tk.z);
            Ks[r * KS_S + c4 * 4 + 3] = f2tf32(tk.w);
            float4 tv = Vg[(kt * 64 + r) * 16 + c4];
            Vs[r * KS_S + c4 * 4 + 0] = f2tf32(tv.x);
            Vs[r * KS_S + c4 * 4 + 1] = f2tf32(tv.y);
            Vs[r * KS_S + c4 * 4 + 2] = f2tf32(tv.z);
            Vs[r * KS_S + c4 * 4 + 3] = f2tf32(tv.w);
        }
        __syncthreads();

        // ---- S = Q K^T : 16(q) x 64(keys) per warp ----
        float sacc[8][4];
        #pragma unroll
        for (int nt = 0; nt < 8; nt++)
            #pragma unroll
            for (int r = 0; r < 4; r++) sacc[nt][r] = 0.f;

        #pragma unroll
        for (int nt = 0; nt < 8; nt++) {
            #pragma unroll
            for (int ks = 0; ks < 8; ks++) {
                uint32_t kb0 = Ks[(nt * 8 + g) * KS_S + ks * 8 + tig];
                uint32_t kb1 = Ks[(nt * 8 + g) * KS_S + ks * 8 + tig + 4];
                mma_tf32(sacc[nt], qa[ks][0], qa[ks][1], qa[ks][2], qa[ks][3], kb0, kb1);
            }
        }

        // ---- online off-by-one softmax on the C fragments ----
        float tm0 = -1e30f, tm1 = -1e30f;
        #pragma unroll
        for (int nt = 0; nt < 8; nt++) {
            tm0 = fmaxf(tm0, fmaxf(sacc[nt][0], sacc[nt][1]));
            tm1 = fmaxf(tm1, fmaxf(sacc[nt][2], sacc[nt][3]));
        }
        tm0 = fmaxf(tm0, __shfl_xor_sync(0xffffffffu, tm0, 1));
        tm0 = fmaxf(tm0, __shfl_xor_sync(0xffffffffu, tm0, 2));
        tm1 = fmaxf(tm1, __shfl_xor_sync(0xffffffffu, tm1, 1));
        tm1 = fmaxf(tm1, __shfl_xor_sync(0xffffffffu, tm1, 2));

        float nm0 = fmaxf(m0, tm0), nm1 = fmaxf(m1, tm1);
        float f0 = __expf(m0 - nm0), f1 = __expf(m1 - nm1);
        m0 = nm0; m1 = nm1;

        uint32_t pc[8][4];
        float ps0 = 0.f, ps1 = 0.f;
        #pragma unroll
        for (int nt = 0; nt < 8; nt++) {
            float p0 = __expf(sacc[nt][0] - m0);
            float p1 = __expf(sacc[nt][1] - m0);
            float p2 = __expf(sacc[nt][2] - m1);
            float p3 = __expf(sacc[nt][3] - m1);
            ps0 += p0 + p1; ps1 += p2 + p3;
            pc[nt][0] = f2tf32(p0); pc[nt][1] = f2tf32(p1);
            pc[nt][2] = f2tf32(p2); pc[nt][3] = f2tf32(p3);
        }
        ps0 += __shfl_xor_sync(0xffffffffu, ps0, 1);
        ps0 += __shfl_xor_sync(0xffffffffu, ps0, 2);
        ps1 += __shfl_xor_sync(0xffffffffu, ps1, 1);
        ps1 += __shfl_xor_sync(0xffffffffu, ps1, 2);
        l0 = l0 * f0 + ps0;
        l1 = l1 * f1 + ps1;

        #pragma unroll
        for (int nt = 0; nt < 8; nt++) {
            oacc[nt][0] *= f0; oacc[nt][1] *= f0;
            oacc[nt][2] *= f1; oacc[nt][3] *= f1;
        }

        // ---- O += P V : rearrange P C-frag -> A-frag (quad shuffles), mma ----
        const int srcA = (lane & ~3) | (tig >> 1);
        const int srcB = srcA + 2;
        #pragma unroll
        for (int ks = 0; ks < 8; ks++) {
            uint32_t v0a = __shfl_sync(0xffffffffu, pc[ks][0], srcA);
            uint32_t v1a = __shfl_sync(0xffffffffu, pc[ks][1], srcA);
            uint32_t v2a = __shfl_sync(0xffffffffu, pc[ks][2], srcA);
            uint32_t v3a = __shfl_sync(0xffffffffu, pc[ks][3], srcA);
            uint32_t v0b = __shfl_sync(0xffffffffu, pc[ks][0], srcB);
            uint32_t v1b = __shfl_sync(0xffffffffu, pc[ks][1], srcB);
            uint32_t v2b = __shfl_sync(0xffffffffu, pc[ks][2], srcB);
            uint32_t v3b = __shfl_sync(0xffffffffu, pc[ks][3], srcB);
            uint32_t pa0 = odd ? v1a : v0a;   // row g,   key ks*8+tig
            uint32_t pa1 = odd ? v3a : v2a;   // row g+8, key ks*8+tig
            uint32_t pa2 = odd ? v1b : v0b;   // row g,   key ks*8+tig+4
            uint32_t pa3 = odd ? v3b : v2b;   // row g+8, key ks*8+tig+4
            #pragma unroll
            for (int nt = 0; nt < 8; nt++) {
                uint32_t vb0 = Vs[(ks * 8 + tig)     * KS_S + nt * 8 + g];
                uint32_t vb1 = Vs[(ks * 8 + tig + 4) * KS_S + nt * 8 + g];
                mma_tf32(oacc[nt], pa0, pa1, pa2, pa3, vb0, vb1);
            }
        }
    }

    // ---- write O with 1/(1+l) and slim ----
    float sl = slim[h];
    float inv0 = sl / (1.0f + l0);
    float inv1 = sl / (1.0f + l1);
    int q0 = qbase + w * 16 + g;
    float* ob0 = out + ((size_t)(b * NSEQ + q0))     * FDIM + h * DHEAD;
    float* ob1 = out + ((size_t)(b * NSEQ + q0 + 8)) * FDIM + h * DHEAD;
    #pragma unroll
    for (int nt = 0; nt < 8; nt++) {
        int d = nt * 8 + tig * 2;
        *reinterpret_cast<float2*>(ob0 + d) =
            make_float2(oacc[nt][0] * inv0, oacc[nt][1] * inv0);
        *reinterpret_cast<float2*>(ob1 + d) =
            make_float2(oacc[nt][2] * inv1, oacc[nt][3] * inv1);
    }
}

// ---------------------------------------------------------------------------
// Launch
// ---------------------------------------------------------------------------
extern "C" void kernel_launch(void* const* d_in, const int* in_sizes, int n_in,
                              void* d_out, int out_size)
{
    const float* x    = (const float*)d_in[0];
    const float* ln1g = (const float*)d_in[1];
    const float* ln1b = (const float*)d_in[2];
    const float* Wq   = (const float*)d_in[3];
    const float* bq   = (const float*)d_in[4];
    const float* Wk   = (const float*)d_in[5];
    const float* bk   = (const float*)d_in[6];
    const float* Wv   = (const float*)d_in[7];
    const float* bv   = (const float*)d_in[8];
    const float* Wo   = (const float*)d_in[9];
    const float* bo   = (const float*)d_in[10];
    const float* slim = (const float*)d_in[11];
    const float* ln2g = (const float*)d_in[12];
    const float* ln2b = (const float*)d_in[13];
    const float* W1   = (const float*)d_in[14];
    const float* b1   = (const float*)d_in[15];
    const float* W2   = (const float*)d_in[16];
    const float* b2   = (const float*)d_in[17];
    float* out = (float*)d_out;

    float *ph, *pq, *pk, *pv, *pa, *po, *ph2, *pm1;
    cudaGetSymbolAddress((void**)&ph,  g_h);
    cudaGetSymbolAddress((void**)&pq,  g_q);
    cudaGetSymbolAddress((void**)&pk,  g_k);
    cudaGetSymbolAddress((void**)&pv,  g_v);
    cudaGetSymbolAddress((void**)&pa,  g_attn);
    cudaGetSymbolAddress((void**)&po,  g_out);
    cudaGetSymbolAddress((void**)&ph2, g_h2);
    cudaGetSymbolAddress((void**)&pm1, g_m1);

    const int SMEM = 4 * TILE_WORDS * 4;   // 67584 bytes
    cudaFuncSetAttribute(sgemm_tf32<false, false, true>,
                         cudaFuncAttributeMaxDynamicSharedMemorySize, SMEM);
    cudaFuncSetAttribute(sgemm_tf32<false, true, false>,
                         cudaFuncAttributeMaxDynamicSharedMemorySize, SMEM);
    cudaFuncSetAttribute(sgemm_tf32<true, false, false>,
                         cudaFuncAttributeMaxDynamicSharedMemorySize, SMEM);
    cudaFuncSetAttribute(sgemm_tf32<true, true, false>,
                         cudaFuncAttributeMaxDynamicSharedMemorySize, SMEM);

    dim3 gF(FDIM / 128, TOK / 128);   // (8, 32)
    dim3 gM(MLPD / 128, TOK / 128);   // (32, 32)

    // 1. LN1
    ln_kernel<<<TOK, 256>>>(x, ln1g, ln1b, ph);

    // 2. Q/K/V projections (scatter into [b,h,n,d])
    sgemm_tf32<false, false, true><<<gF, 256, SMEM>>>(ph, Wq, bq, nullptr, pq, TOK, FDIM, FDIM);
    sgemm_tf32<false, false, true><<<gF, 256, SMEM>>>(ph, Wk, bk, nullptr, pk, TOK, FDIM, FDIM);
    sgemm_tf32<false, false, true><<<gF, 256, SMEM>>>(ph, Wv, bv, nullptr, pv, TOK, FDIM, FDIM);

    // 3. Attention (tensor-core flash, off-by-one softmax + slim)
    attn_mma<<<dim3(2 * NHEAD, NSEQ / 64), 128>>>(pq, pk, pv, slim, pa);

    // 4. Output projection + residual 1
    sgemm_tf32<false, true, false><<<gF, 256, SMEM>>>(pa, Wo, bo, x, po, TOK, FDIM, FDIM);

    // 5. LN2
    ln_kernel<<<TOK, 256>>>(po, ln2g, ln2b, ph2);

    // 6. MLP up + GELU
    sgemm_tf32<true, false, false><<<gM, 256, SMEM>>>(ph2, W1, b1, nullptr, pm1, TOK, MLPD, FDIM);

    // 7. MLP down + GELU + residual 2 -> final output
    sgemm_tf32<true, true, false><<<gF, 256, SMEM>>>(pm1, W2, b2, po, out, TOK, FDIM, MLPD);
}

// round 10
// speedup vs baseline: 6.8751x; 1.6226x over previous
#include <cuda_runtime.h>
#include <cuda_fp16.h>
#include <math.h>
#include <stdint.h>

#define TOK   4096
#define FDIM  1024
#define NHEAD 16
#define DHEAD 64
#define MLPD  4096
#define NSEQ  2048

// ---------------------------------------------------------------------------
// Scratch (device globals: allocation-free per harness rules)
// ---------------------------------------------------------------------------
__device__ float g_h   [TOK * FDIM];   // LN1 output
__device__ float g_q   [TOK * FDIM];   // [b][h][n][dh]
__device__ float g_k   [TOK * FDIM];   // [b][h][n][dh]
__device__ float g_v   [TOK * FDIM];   // [b][h][n][dh]
__device__ float g_attn[TOK * FDIM];   // [token][f]
__device__ float g_out [TOK * FDIM];   // residual-1 output
__device__ float g_h2  [TOK * FDIM];   // LN2 output
__device__ float g_m1  [TOK * MLPD];   // MLP hidden

__device__ __forceinline__ float gelu_exact(float x) {
    return 0.5f * x * (1.0f + erff(x * 0.70710678118654752f));
}

__device__ __forceinline__ uint32_t f2tf32(float x) {
    uint32_t r;
    asm("cvt.rna.tf32.f32 %0, %1;" : "=r"(r) : "f"(x));
    return r;
}

__device__ __forceinline__ uint32_t pack_h2(float lo, float hi) {
    __half2 h = __floats2half2_rn(lo, hi);
    return *reinterpret_cast<uint32_t*>(&h);
}

__device__ __forceinline__ void mma_tf32(float c[4],
                                         uint32_t a0, uint32_t a1, uint32_t a2, uint32_t a3,
                                         uint32_t b0, uint32_t b1) {
    asm volatile(
        "mma.sync.aligned.m16n8k8.row.col.f32.tf32.tf32.f32 "
        "{%0,%1,%2,%3}, {%4,%5,%6,%7}, {%8,%9}, {%0,%1,%2,%3};"
        : "+f"(c[0]), "+f"(c[1]), "+f"(c[2]), "+f"(c[3])
        : "r"(a0), "r"(a1), "r"(a2), "r"(a3), "r"(b0), "r"(b1));
}

__device__ __forceinline__ void mma_f16(float c[4],
                                        uint32_t a0, uint32_t a1, uint32_t a2, uint32_t a3,
                                        uint32_t b0, uint32_t b1) {
    asm volatile(
        "mma.sync.aligned.m16n8k16.row.col.f32.f16.f16.f32 "
        "{%0,%1,%2,%3}, {%4,%5,%6,%7}, {%8,%9}, {%0,%1,%2,%3};"
        : "+f"(c[0]), "+f"(c[1]), "+f"(c[2]), "+f"(c[3])
        : "r"(a0), "r"(a1), "r"(a2), "r"(a3), "r"(b0), "r"(b1));
}

// ---------------------------------------------------------------------------
// LayerNorm: one block per row (1024 floats), 256 threads, 1 float4 each
// ---------------------------------------------------------------------------
__global__ void __launch_bounds__(256) ln_kernel(const float* __restrict__ x,
                                                 const float* __restrict__ g,
                                                 const float* __restrict__ b,
                                                 float* __restrict__ out) {
    int row = blockIdx.x;
    const float4* xr = reinterpret_cast<const float4*>(x + (size_t)row * FDIM);
    float4 v = xr[threadIdx.x];

    float s  = v.x + v.y + v.z + v.w;
    float s2 = v.x * v.x + v.y * v.y + v.z * v.z + v.w * v.w;

    #pragma unroll
    for (int o = 16; o > 0; o >>= 1) {
        s  += __shfl_xor_sync(0xffffffffu, s,  o);
        s2 += __shfl_xor_sync(0xffffffffu, s2, o);
    }
    __shared__ float ss[8], ss2[8];
    int w = threadIdx.x >> 5, lane = threadIdx.x & 31;
    if (lane == 0) { ss[w] = s; ss2[w] = s2; }
    __syncthreads();
    s = 0.f; s2 = 0.f;
    #pragma unroll
    for (int i = 0; i < 8; i++) { s += ss[i]; s2 += ss2[i]; }

    float mu  = s * (1.0f / FDIM);
    float var = s2 * (1.0f / FDIM) - mu * mu;
    float r   = rsqrtf(var + 1e-5f);

    float4 gg = reinterpret_cast<const float4*>(g)[threadIdx.x];
    float4 bb = reinterpret_cast<const float4*>(b)[threadIdx.x];
    float4 o4;
    o4.x = (v.x - mu) * r * gg.x + bb.x;
    o4.y = (v.y - mu) * r * gg.y + bb.y;
    o4.z = (v.z - mu) * r * gg.z + bb.z;
    o4.w = (v.w - mu) * r * gg.w + bb.w;
    reinterpret_cast<float4*>(out + (size_t)row * FDIM)[threadIdx.x] = o4;
}

// ---------------------------------------------------------------------------
// FP16 tensor-core GEMM (fp32 accumulate), double-buffered.
// C[M,N] = A[M,K] @ B[K,N] + bias, fused epilogue (GELU/RES/QKV-scatter).
// BM=BN=128, BK=32, 256 threads = 8 warps (2 m x 4 n), warp tile 64x32.
// mma.m16n8k16. Smem: half2-packed k-pairs, [k/2][m] and [k/2][n].
// Static smem: 2 x 2 x 16 x 132 words = 33792 B.
// ---------------------------------------------------------------------------
#define TS 132
#define TILE_WORDS (16 * TS)

template <bool GELU, bool RES, bool QKV>
__global__ void __launch_bounds__(256) hgemm(
    const float* __restrict__ A, const float* __restrict__ B,
    const float* __restrict__ bias, const float* __restrict__ res,
    float* __restrict__ C, int M, int N, int K)
{
    __shared__ uint32_t As[2 * TILE_WORDS];   // [2][16][132] half2 (k-pair, m)
    __shared__ uint32_t Bs[2 * TILE_WORDS];   // [2][16][132] half2 (k-pair, n)

    const int tid    = threadIdx.x;
    const int warp   = tid >> 5;
    const int lane   = tid & 31;
    const int g      = lane >> 2;      // 0..7
    const int tig    = lane & 3;       // 0..3
    const int warp_m = (warp & 1) * 64;
    const int warp_n = (warp >> 1) * 32;

    const float* Ab = A + (size_t)blockIdx.y * 128 * K;
    const float* Bb = B + blockIdx.x * 128;

    // tile-load coordinates
    const int ar = tid >> 3, ac = tid & 7;    // A: rows ar+t*32, k cols ac*4..+3
    const int br = tid >> 5, bc = tid & 31;   // B: k-pairs br+t*8, n cols bc*4..+3

    float acc[4][4][4];
    #pragma unroll
    for (int mt = 0; mt < 4; mt++)
        #pragma unroll
        for (int nt = 0; nt < 4; nt++)
            #pragma unroll
            for (int r = 0; r < 4; r++) acc[mt][nt][r] = 0.f;

    const int nk = K >> 5;

    // ---- prologue: tile 0 into buffer 0 ----
    {
        #pragma unroll
        for (int t = 0; t < 4; t++) {
            int r = ar + t * 32;
            float4 av = *reinterpret_cast<const float4*>(Ab + (size_t)r * K + ac * 4);
            As[(ac * 2 + 0) * TS + r] = pack_h2(av.x, av.y);
            As[(ac * 2 + 1) * TS + r] = pack_h2(av.z, av.w);
        }
        #pragma unroll
        for (int t = 0; t < 2; t++) {
            int p = br + t * 8;                       // k-pair 0..15
            float4 b0 = *reinterpret_cast<const float4*>(Bb + (size_t)(2 * p)     * N + bc * 4);
            float4 b1 = *reinterpret_cast<const float4*>(Bb + (size_t)(2 * p + 1) * N + bc * 4);
            uint4 bu;
            bu.x = pack_h2(b0.x, b1.x); bu.y = pack_h2(b0.y, b1.y);
            bu.z = pack_h2(b0.z, b1.z); bu.w = pack_h2(b0.w, b1.w);
            *reinterpret_cast<uint4*>(&Bs[p * TS + bc * 4]) = bu;
        }
    }
    __syncthreads();

    for (int kt = 0; kt < nk; kt++) {
        const uint32_t* Ac = As + (kt & 1) * TILE_WORDS;
        const uint32_t* Bc = Bs + (kt & 1) * TILE_WORDS;
        uint32_t* An = As + ((kt + 1) & 1) * TILE_WORDS;
        uint32_t* Bn = Bs + ((kt + 1) & 1) * TILE_WORDS;

        // issue next tile's global loads first (hidden under mma)
        float4 av[4], bv0[2], bv1[2];
        if (kt + 1 < nk) {
            int k0 = (kt + 1) << 5;
            #pragma unroll
            for (int t = 0; t < 4; t++)
                av[t] = *reinterpret_cast<const float4*>(Ab + (size_t)(ar + t * 32) * K + k0 + ac * 4);
            #pragma unroll
            for (int t = 0; t < 2; t++) {
                int p = br + t * 8;
                bv0[t] = *reinterpret_cast<const float4*>(Bb + (size_t)(k0 + 2 * p)     * N + bc * 4);
                bv1[t] = *reinterpret_cast<const float4*>(Bb + (size_t)(k0 + 2 * p + 1) * N + bc * 4);
            }
        }

        // ---- compute current tile: 2 k16 steps ----
        #pragma unroll
        for (int ks = 0; ks < 2; ks++) {
            uint32_t af[4][4], bf[4][2];
            #pragma unroll
            for (int mt = 0; mt < 4; mt++) {
                int mrow = warp_m + mt * 16 + g;
                af[mt][0] = Ac[(ks * 8 + tig)     * TS + mrow];
                af[mt][1] = Ac[(ks * 8 + tig)     * TS + mrow + 8];
                af[mt][2] = Ac[(ks * 8 + tig + 4) * TS + mrow];
                af[mt][3] = Ac[(ks * 8 + tig + 4) * TS + mrow + 8];
            }
            #pragma unroll
            for (int nt = 0; nt < 4; nt++) {
                int ncol = warp_n + nt * 8 + g;
                bf[nt][0] = Bc[(ks * 8 + tig)     * TS + ncol];
                bf[nt][1] = Bc[(ks * 8 + tig + 4) * TS + ncol];
            }
            #pragma unroll
            for (int mt = 0; mt < 4; mt++)
                #pragma unroll
                for (int nt = 0; nt < 4; nt++)
                    mma_f16(acc[mt][nt], af[mt][0], af[mt][1], af[mt][2], af[mt][3],
                            bf[nt][0], bf[nt][1]);
        }

        // ---- stash next tile ----
        if (kt + 1 < nk) {
            #pragma unroll
            for (int t = 0; t < 4; t++) {
                int r = ar + t * 32;
                An[(ac * 2 + 0) * TS + r] = pack_h2(av[t].x, av[t].y);
                An[(ac * 2 + 1) * TS + r] = pack_h2(av[t].z, av[t].w);
            }
            #pragma unroll
            for (int t = 0; t < 2; t++) {
                int p = br + t * 8;
                uint4 bu;
                bu.x = pack_h2(bv0[t].x, bv1[t].x); bu.y = pack_h2(bv0[t].y, bv1[t].y);
                bu.z = pack_h2(bv0[t].z, bv1[t].z); bu.w = pack_h2(bv0[t].w, bv1[t].w);
                *reinterpret_cast<uint4*>(&Bn[p * TS + bc * 4]) = bu;
            }
        }
        __syncthreads();
    }

    // --- Epilogue (C layout of m16n8k16 == m16n8k8) ---
    const int rowbase = blockIdx.y * 128 + warp_m;
    const int colbase = blockIdx.x * 128 + warp_n;

    #pragma unroll
    for (int mt = 0; mt < 4; mt++) {
        #pragma unroll
        for (int nt = 0; nt < 4; nt++) {
            int c = colbase + nt * 8 + tig * 2;
            float bx = bias[c], by = bias[c + 1];
            #pragma unroll
            for (int half = 0; half < 2; half++) {
                int r = rowbase + mt * 16 + g + half * 8;
                float v0 = acc[mt][nt][half * 2 + 0] + bx;
                float v1 = acc[mt][nt][half * 2 + 1] + by;
                if (GELU) { v0 = gelu_exact(v0); v1 = gelu_exact(v1); }
                if (RES) {
                    float2 rr = *reinterpret_cast<const float2*>(res + (size_t)r * N + c);
                    v0 += rr.x; v1 += rr.y;
                }
                float2 ov = make_float2(v0, v1);
                if (QKV) {
                    int b = r >> 11;
                    int n = r & 2047;
                    int h = c >> 6;
                    int d = c & 63;
                    *reinterpret_cast<float2*>(
                        C + ((size_t)((b * NHEAD + h) * NSEQ + n)) * DHEAD + d) = ov;
                } else {
                    *reinterpret_cast<float2*>(C + (size_t)r * N + c) = ov;
                }
            }
        }
    }
}

// ---------------------------------------------------------------------------
// Tensor-core flash attention (tf32), off-by-one softmax + per-head slimming.
// q/k/v layout: [b][h][n][dh]. out: [token][FDIM].
// Block: 128 threads (4 warps); q-tile 64 rows (16/warp); k-tiles of 64 keys.
// ---------------------------------------------------------------------------
#define KS_S 68

__global__ void __launch_bounds__(128) attn_mma(
    const float* __restrict__ q, const float* __restrict__ k,
    const float* __restrict__ v, const float* __restrict__ slim,
    float* __restrict__ out)
{
    __shared__ uint32_t Ks[64 * KS_S];
    __shared__ uint32_t Vs[64 * KS_S];

    const int bh = blockIdx.x;          // 0..31
    const int b  = bh >> 4;
    const int h  = bh & 15;
    const int qbase = blockIdx.y * 64;

    const int tid  = threadIdx.x;
    const int w    = tid >> 5;
    const int lane = tid & 31;
    const int g    = lane >> 2;         // 0..7
    const int tig  = lane & 3;          // 0..3
    const bool odd = tig & 1;

    // ---- stage Q (scaled by 1/8, tf32) through Ks, extract A-fragments ----
    const float4* Qg = reinterpret_cast<const float4*>(
        q + ((size_t)bh * NSEQ + qbase) * DHEAD);
    #pragma unroll
    for (int i = 0; i < 8; i++) {
        int idx = tid + i * 128;        // 0..1023
        int r = idx >> 4, c4 = idx & 15;
        float4 t = Qg[r * 16 + c4];
        Ks[r * KS_S + c4 * 4 + 0] = f2tf32(t.x * 0.125f);
        Ks[r * KS_S + c4 * 4 + 1] = f2tf32(t.y * 0.125f);
        Ks[r * KS_S + c4 * 4 + 2] = f2tf32(t.z * 0.125f);
        Ks[r * KS_S + c4 * 4 + 3] = f2tf32(t.w * 0.125f);
    }
    __syncthreads();

    uint32_t qa[8][4];
    {
        int row0 = w * 16 + g;
        #pragma unroll
        for (int ks = 0; ks < 8; ks++) {
            qa[ks][0] = Ks[ row0      * KS_S + ks * 8 + tig];
            qa[ks][1] = Ks[(row0 + 8) * KS_S + ks * 8 + tig];
            qa[ks][2] = Ks[ row0      * KS_S + ks * 8 + tig + 4];
            qa[ks][3] = Ks[(row0 + 8) * KS_S + ks * 8 + tig + 4];
        }
    }

    float oacc[8][4];
    #pragma unroll
    for (int nt = 0; nt < 8; nt++)
        #pragma unroll
        for (int r = 0; r < 4; r++) oacc[nt][r] = 0.f;
    float m0 = -1e30f, m1 = -1e30f, l0 = 0.f, l1 = 0.f;

    const float4* Kg = reinterpret_cast<const float4*>(k + (size_t)bh * NSEQ * DHEAD);
    const float4* Vg = reinterpret_cast<const float4*>(v + (size_t)bh * NSEQ * DHEAD);

    for (int kt = 0; kt < NSEQ / 64; kt++) {
        __syncthreads();   // previous tile fully consumed (also guards Q frags, iter 0)
        #pragma unroll
        for (int i = 0; i < 8; i++) {
            int idx = tid + i * 128;
            int r = idx >> 4, c4 = idx & 15;
            float4 tk = Kg[(kt * 64 + r) * 16 + c4];
            Ks[r * KS_S + c4 * 4 + 0] = f2tf32(tk.x);
            Ks[r * KS_S + c4 * 4 + 1] = f2tf32(tk.y);
            Ks[r * KS_S + c4 * 4 + 2] = f2tf32(tk.z);
            Ks[r * KS_S + c4 * 4 + 3] = f2tf32(tk.w);
            float4 tv = Vg[(kt * 64 + r) * 16 + c4];
            Vs[r * KS_S + c4 * 4 + 0] = f2tf32(tv.x);
            Vs[r * KS_S + c4 * 4 + 1] = f2tf32(tv.y);
            Vs[r * KS_S + c4 * 4 + 2] = f2tf32(tv.z);
            Vs[r * KS_S + c4 * 4 + 3] = f2tf32(tv.w);
        }
        __syncthreads();

        // ---- S = Q K^T : 16(q) x 64(keys) per warp ----
        float sacc[8][4];
        #pragma unroll
        for (int nt = 0; nt < 8; nt++)
            #pragma unroll
            for (int r = 0; r < 4; r++) sacc[nt][r] = 0.f;

        #pragma unroll
        for (int nt = 0; nt < 8; nt++) {
            #pragma unroll
            for (int ks = 0; ks < 8; ks++) {
                uint32_t kb0 = Ks[(nt * 8 + g) * KS_S + ks * 8 + tig];
                uint32_t kb1 = Ks[(nt * 8 + g) * KS_S + ks * 8 + tig + 4];
                mma_tf32(sacc[nt], qa[ks][0], qa[ks][1], qa[ks][2], qa[ks][3], kb0, kb1);
            }
        }

        // ---- online off-by-one softmax on the C fragments ----
        float tm0 = -1e30f, tm1 = -1e30f;
        #pragma unroll
        for (int nt = 0; nt < 8; nt++) {
            tm0 = fmaxf(tm0, fmaxf(sacc[nt][0], sacc[nt][1]));
            tm1 = fmaxf(tm1, fmaxf(sacc[nt][2], sacc[nt][3]));
        }
        tm0 = fmaxf(tm0, __shfl_xor_sync(0xffffffffu, tm0, 1));
        tm0 = fmaxf(tm0, __shfl_xor_sync(0xffffffffu, tm0, 2));
        tm1 = fmaxf(tm1, __shfl_xor_sync(0xffffffffu, tm1, 1));
        tm1 = fmaxf(tm1, __shfl_xor_sync(0xffffffffu, tm1, 2));

        float nm0 = fmaxf(m0, tm0), nm1 = fmaxf(m1, tm1);
        float f0 = __expf(m0 - nm0), f1 = __expf(m1 - nm1);
        m0 = nm0; m1 = nm1;

        uint32_t pc[8][4];
        float ps0 = 0.f, ps1 = 0.f;
        #pragma unroll
        for (int nt = 0; nt < 8; nt++) {
            float p0 = __expf(sacc[nt][0] - m0);
            float p1 = __expf(sacc[nt][1] - m0);
            float p2 = __expf(sacc[nt][2] - m1);
            float p3 = __expf(sacc[nt][3] - m1);
            ps0 += p0 + p1; ps1 += p2 + p3;
            pc[nt][0] = f2tf32(p0); pc[nt][1] = f2tf32(p1);
            pc[nt][2] = f2tf32(p2); pc[nt][3] = f2tf32(p3);
        }
        ps0 += __shfl_xor_sync(0xffffffffu, ps0, 1);
        ps0 += __shfl_xor_sync(0xffffffffu, ps0, 2);
        ps1 += __shfl_xor_sync(0xffffffffu, ps1, 1);
        ps1 += __shfl_xor_sync(0xffffffffu, ps1, 2);
        l0 = l0 * f0 + ps0;
        l1 = l1 * f1 + ps1;

        #pragma unroll
        for (int nt = 0; nt < 8; nt++) {
            oacc[nt][0] *= f0; oacc[nt][1] *= f0;
            oacc[nt][2] *= f1; oacc[nt][3] *= f1;
        }

        // ---- O += P V : rearrange P C-frag -> A-frag (quad shuffles), mma ----
        const int srcA = (lane & ~3) | (tig >> 1);
        const int srcB = srcA + 2;
        #pragma unroll
        for (int ks = 0; ks < 8; ks++) {
            uint32_t v0a = __shfl_sync(0xffffffffu, pc[ks][0], srcA);
            uint32_t v1a = __shfl_sync(0xffffffffu, pc[ks][1], srcA);
            uint32_t v2a = __shfl_sync(0xffffffffu, pc[ks][2], srcA);
            uint32_t v3a = __shfl_sync(0xffffffffu, pc[ks][3], srcA);
            uint32_t v0b = __shfl_sync(0xffffffffu, pc[ks][0], srcB);
            uint32_t v1b = __shfl_sync(0xffffffffu, pc[ks][1], srcB);
            uint32_t v2b = __shfl_sync(0xffffffffu, pc[ks][2], srcB);
            uint32_t v3b = __shfl_sync(0xffffffffu, pc[ks][3], srcB);
            uint32_t pa0 = odd ? v1a : v0a;   // row g,   key ks*8+tig
            uint32_t pa1 = odd ? v3a : v2a;   // row g+8, key ks*8+tig
            uint32_t pa2 = odd ? v1b : v0b;   // row g,   key ks*8+tig+4
            uint32_t pa3 = odd ? v3b : v2b;   // row g+8, key ks*8+tig+4
            #pragma unroll
            for (int nt = 0; nt < 8; nt++) {
                uint32_t vb0 = Vs[(ks * 8 + tig)     * KS_S + nt * 8 + g];
                uint32_t vb1 = Vs[(ks * 8 + tig + 4) * KS_S + nt * 8 + g];
                mma_tf32(oacc[nt], pa0, pa1, pa2, pa3, vb0, vb1);
            }
        }
    }

    // ---- write O with 1/(1+l) and slim ----
    float sl = slim[h];
    float inv0 = sl / (1.0f + l0);
    float inv1 = sl / (1.0f + l1);
    int q0 = qbase + w * 16 + g;
    float* ob0 = out + ((size_t)(b * NSEQ + q0))     * FDIM + h * DHEAD;
    float* ob1 = out + ((size_t)(b * NSEQ + q0 + 8)) * FDIM + h * DHEAD;
    #pragma unroll
    for (int nt = 0; nt < 8; nt++) {
        int d = nt * 8 + tig * 2;
        *reinterpret_cast<float2*>(ob0 + d) =
            make_float2(oacc[nt][0] * inv0, oacc[nt][1] * inv0);
        *reinterpret_cast<float2*>(ob1 + d) =
            make_float2(oacc[nt][2] * inv1, oacc[nt][3] * inv1);
    }
}

// ---------------------------------------------------------------------------
// Launch
// ---------------------------------------------------------------------------
extern "C" void kernel_launch(void* const* d_in, const int* in_sizes, int n_in,
                              void* d_out, int out_size)
{
    const float* x    = (const float*)d_in[0];
    const float* ln1g = (const float*)d_in[1];
    const float* ln1b = (const float*)d_in[2];
    const float* Wq   = (const float*)d_in[3];
    const float* bq   = (const float*)d_in[4];
    const float* Wk   = (const float*)d_in[5];
    const float* bk   = (const float*)d_in[6];
    const float* Wv   = (const float*)d_in[7];
    const float* bv   = (const float*)d_in[8];
    const float* Wo   = (const float*)d_in[9];
    const float* bo   = (const float*)d_in[10];
    const float* slim = (const float*)d_in[11];
    const float* ln2g = (const float*)d_in[12];
    const float* ln2b = (const float*)d_in[13];
    const float* W1   = (const float*)d_in[14];
    const float* b1   = (const float*)d_in[15];
    const float* W2   = (const float*)d_in[16];
    const float* b2   = (const float*)d_in[17];
    float* out = (float*)d_out;

    float *ph, *pq, *pk, *pv, *pa, *po, *ph2, *pm1;
    cudaGetSymbolAddress((void**)&ph,  g_h);
    cudaGetSymbolAddress((void**)&pq,  g_q);
    cudaGetSymbolAddress((void**)&pk,  g_k);
    cudaGetSymbolAddress((void**)&pv,  g_v);
    cudaGetSymbolAddress((void**)&pa,  g_attn);
    cudaGetSymbolAddress((void**)&po,  g_out);
    cudaGetSymbolAddress((void**)&ph2, g_h2);
    cudaGetSymbolAddress((void**)&pm1, g_m1);

    dim3 gF(FDIM / 128, TOK / 128);   // (8, 32)
    dim3 gM(MLPD / 128, TOK / 128);   // (32, 32)

    // 1. LN1
    ln_kernel<<<TOK, 256>>>(x, ln1g, ln1b, ph);

    // 2. Q/K/V projections (scatter into [b,h,n,d])
    hgemm<false, false, true><<<gF, 256>>>(ph, Wq, bq, nullptr, pq, TOK, FDIM, FDIM);
    hgemm<false, false, true><<<gF, 256>>>(ph, Wk, bk, nullptr, pk, TOK, FDIM, FDIM);
    hgemm<false, false, true><<<gF, 256>>>(ph, Wv, bv, nullptr, pv, TOK, FDIM, FDIM);

    // 3. Attention (tensor-core flash, off-by-one softmax + slim)
    attn_mma<<<dim3(2 * NHEAD, NSEQ / 64), 128>>>(pq, pk, pv, slim, pa);

    // 4. Output projection + residual 1
    hgemm<false, true, false><<<gF, 256>>>(pa, Wo, bo, x, po, TOK, FDIM, FDIM);

    // 5. LN2
    ln_kernel<<<TOK, 256>>>(po, ln2g, ln2b, ph2);

    // 6. MLP up + GELU
    hgemm<true, false, false><<<gM, 256>>>(ph2, W1, b1, nullptr, pm1, TOK, MLPD, FDIM);

    // 7. MLP down + GELU + residual 2 -> final output
    hgemm<true, true, false><<<gF, 256>>>(pm1, W2, b2, po, out, TOK, FDIM, MLPD);
}

// round 11
// speedup vs baseline: 8.0039x; 1.1642x over previous
#include <cuda_runtime.h>
#include <cuda_fp16.h>
#include <math.h>
#include <stdint.h>

#define TOK   4096
#define FDIM  1024
#define NHEAD 16
#define DHEAD 64
#define MLPD  4096
#define NSEQ  2048

// ---------------------------------------------------------------------------
// Scratch (device globals: allocation-free per harness rules)
// ---------------------------------------------------------------------------
__device__ float g_h   [TOK * FDIM];   // LN1 output
__device__ float g_q   [TOK * FDIM];   // [b][h][n][dh]
__device__ float g_k   [TOK * FDIM];   // [b][h][n][dh]
__device__ float g_v   [TOK * FDIM];   // [b][h][n][dh]
__device__ float g_attn[TOK * FDIM];   // [token][f]
__device__ float g_out [TOK * FDIM];   // residual-1 output
__device__ float g_h2  [TOK * FDIM];   // LN2 output
__device__ float g_m1  [TOK * MLPD];   // MLP hidden

__device__ __forceinline__ float gelu_exact(float x) {
    return 0.5f * x * (1.0f + erff(x * 0.70710678118654752f));
}

__device__ __forceinline__ uint32_t f2tf32(float x) {
    uint32_t r;
    asm("cvt.rna.tf32.f32 %0, %1;" : "=r"(r) : "f"(x));
    return r;
}

__device__ __forceinline__ uint32_t pack_h2(float lo, float hi) {
    __half2 h = __floats2half2_rn(lo, hi);
    return *reinterpret_cast<uint32_t*>(&h);
}

__device__ __forceinline__ void mma_tf32(float c[4],
                                         uint32_t a0, uint32_t a1, uint32_t a2, uint32_t a3,
                                         uint32_t b0, uint32_t b1) {
    asm volatile(
        "mma.sync.aligned.m16n8k8.row.col.f32.tf32.tf32.f32 "
        "{%0,%1,%2,%3}, {%4,%5,%6,%7}, {%8,%9}, {%0,%1,%2,%3};"
        : "+f"(c[0]), "+f"(c[1]), "+f"(c[2]), "+f"(c[3])
        : "r"(a0), "r"(a1), "r"(a2), "r"(a3), "r"(b0), "r"(b1));
}

__device__ __forceinline__ void mma_f16(float c[4],
                                        uint32_t a0, uint32_t a1, uint32_t a2, uint32_t a3,
                                        uint32_t b0, uint32_t b1) {
    asm volatile(
        "mma.sync.aligned.m16n8k16.row.col.f32.f16.f16.f32 "
        "{%0,%1,%2,%3}, {%4,%5,%6,%7}, {%8,%9}, {%0,%1,%2,%3};"
        : "+f"(c[0]), "+f"(c[1]), "+f"(c[2]), "+f"(c[3])
        : "r"(a0), "r"(a1), "r"(a2), "r"(a3), "r"(b0), "r"(b1));
}

__device__ __forceinline__ void ldsm_x4(uint32_t& r0, uint32_t& r1,
                                        uint32_t& r2, uint32_t& r3,
                                        const __half* p) {
    uint32_t a = (uint32_t)__cvta_generic_to_shared(p);
    asm volatile("ldmatrix.sync.aligned.m8n8.x4.shared.b16 {%0,%1,%2,%3}, [%4];"
                 : "=r"(r0), "=r"(r1), "=r"(r2), "=r"(r3) : "r"(a));
}

__device__ __forceinline__ void ldsm_x4_t(uint32_t& r0, uint32_t& r1,
                                          uint32_t& r2, uint32_t& r3,
                                          const __half* p) {
    uint32_t a = (uint32_t)__cvta_generic_to_shared(p);
    asm volatile("ldmatrix.sync.aligned.m8n8.x4.trans.shared.b16 {%0,%1,%2,%3}, [%4];"
                 : "=r"(r0), "=r"(r1), "=r"(r2), "=r"(r3) : "r"(a));
}

// ---------------------------------------------------------------------------
// LayerNorm: one block per row (1024 floats), 256 threads, 1 float4 each
// ---------------------------------------------------------------------------
__global__ void __launch_bounds__(256) ln_kernel(const float* __restrict__ x,
                                                 const float* __restrict__ g,
                                                 const float* __restrict__ b,
                                                 float* __restrict__ out) {
    int row = blockIdx.x;
    const float4* xr = reinterpret_cast<const float4*>(x + (size_t)row * FDIM);
    float4 v = xr[threadIdx.x];

    float s  = v.x + v.y + v.z + v.w;
    float s2 = v.x * v.x + v.y * v.y + v.z * v.z + v.w * v.w;

    #pragma unroll
    for (int o = 16; o > 0; o >>= 1) {
        s  += __shfl_xor_sync(0xffffffffu, s,  o);
        s2 += __shfl_xor_sync(0xffffffffu, s2, o);
    }
    __shared__ float ss[8], ss2[8];
    int w = threadIdx.x >> 5, lane = threadIdx.x & 31;
    if (lane == 0) { ss[w] = s; ss2[w] = s2; }
    __syncthreads();
    s = 0.f; s2 = 0.f;
    #pragma unroll
    for (int i = 0; i < 8; i++) { s += ss[i]; s2 += ss2[i]; }

    float mu  = s * (1.0f / FDIM);
    float var = s2 * (1.0f / FDIM) - mu * mu;
    float r   = rsqrtf(var + 1e-5f);

    float4 gg = reinterpret_cast<const float4*>(g)[threadIdx.x];
    float4 bb = reinterpret_cast<const float4*>(b)[threadIdx.x];
    float4 o4;
    o4.x = (v.x - mu) * r * gg.x + bb.x;
    o4.y = (v.y - mu) * r * gg.y + bb.y;
    o4.z = (v.z - mu) * r * gg.z + bb.z;
    o4.w = (v.w - mu) * r * gg.w + bb.w;
    reinterpret_cast<float4*>(out + (size_t)row * FDIM)[threadIdx.x] = o4;
}

// ---------------------------------------------------------------------------
// FP16 tensor-core GEMM body (fp32 accumulate), double-buffered, ldmatrix.
// C[M,N] = A[M,K] @ B[K,N] + bias, fused epilogue (GELU/RES/QKV-scatter).
// BM=BN=128, BK=32, 256 threads = 8 warps (2 m x 4 n), warp tile 64x32.
// Smem: A [m 128][k 32] pad->40 halfs/row;  B [k 32][n 128] pad->136 halfs/row.
// Fragments via ldmatrix.x4 (A) / ldmatrix.x4.trans (B): 12 LDSM + 32 HMMA
// per 32-k slab per warp.
// ---------------------------------------------------------------------------
#define A_STRIDE 40
#define B_STRIDE 136
#define A_TILE (128 * A_STRIDE)
#define B_TILE (32 * B_STRIDE)

template <bool GELU, bool RES, bool QKV>
__device__ __forceinline__ void gemm_body(
    const float* __restrict__ A, const float* __restrict__ B,
    const float* __restrict__ bias, const float* __restrict__ res,
    float* __restrict__ C, int M, int N, int K,
    __half* Ash, __half* Bsh, int bx, int by)
{
    const int tid    = threadIdx.x;
    const int warp   = tid >> 5;
    const int lane   = tid & 31;
    const int g      = lane >> 2;      // 0..7
    const int tig    = lane & 3;       // 0..3
    const int lane15 = lane & 15;
    const int lhalf  = lane >> 4;      // 0/1
    const int warp_m = (warp & 1) * 64;
    const int warp_n = (warp >> 1) * 32;

    const float* Ab = A + (size_t)by * 128 * K;
    const float* Bb = B + bx * 128;

    // tile-load coordinates
    const int ar = tid >> 3, ac = tid & 7;    // A: rows ar+t*32, k cols ac*4..+3
    const int br = tid >> 5, bc = tid & 31;   // B: k rows br+t*8, n cols bc*4..+3

    float acc[4][4][4];
    #pragma unroll
    for (int mt = 0; mt < 4; mt++)
        #pragma unroll
        for (int nt = 0; nt < 4; nt++)
            #pragma unroll
            for (int r = 0; r < 4; r++) acc[mt][nt][r] = 0.f;

    const int nk = K >> 5;

    // ---- prologue: tile 0 into buffer 0 ----
    {
        #pragma unroll
        for (int t = 0; t < 4; t++) {
            int r = ar + t * 32;
            float4 av = *reinterpret_cast<const float4*>(Ab + (size_t)r * K + ac * 4);
            uint2 u = make_uint2(pack_h2(av.x, av.y), pack_h2(av.z, av.w));
            *reinterpret_cast<uint2*>(Ash + r * A_STRIDE + ac * 4) = u;
        }
        #pragma unroll
        for (int t = 0; t < 4; t++) {
            int r = br + t * 8;
            float4 bv = *reinterpret_cast<const float4*>(Bb + (size_t)r * N + bc * 4);
            uint2 u = make_uint2(pack_h2(bv.x, bv.y), pack_h2(bv.z, bv.w));
            *reinterpret_cast<uint2*>(Bsh + r * B_STRIDE + bc * 4) = u;
        }
    }
    __syncthreads();

    for (int kt = 0; kt < nk; kt++) {
        const __half* Ac = Ash + (kt & 1) * A_TILE;
        const __half* Bc = Bsh + (kt & 1) * B_TILE;
        __half* An = Ash + ((kt + 1) & 1) * A_TILE;
        __half* Bn = Bsh + ((kt + 1) & 1) * B_TILE;

        // issue next tile's global loads first (hidden under mma)
        float4 av[4], bv[4];
        if (kt + 1 < nk) {
            int k0 = (kt + 1) << 5;
            #pragma unroll
            for (int t = 0; t < 4; t++)
                av[t] = *reinterpret_cast<const float4*>(Ab + (size_t)(ar + t * 32) * K + k0 + ac * 4);
            #pragma unroll
            for (int t = 0; t < 4; t++)
                bv[t] = *reinterpret_cast<const float4*>(Bb + (size_t)(k0 + br + t * 8) * N + bc * 4);
        }

        // ---- compute current tile: 2 k16 steps, ldmatrix fragments ----
        #pragma unroll
        for (int ks = 0; ks < 2; ks++) {
            uint32_t af[4][4], bf[4][2];
            #pragma unroll
            for (int mt = 0; mt < 4; mt++)
                ldsm_x4(af[mt][0], af[mt][1], af[mt][2], af[mt][3],
                        Ac + (warp_m + mt * 16 + lane15) * A_STRIDE + ks * 16 + lhalf * 8);
            #pragma unroll
            for (int ntp = 0; ntp < 2; ntp++)
                ldsm_x4_t(bf[2 * ntp][0], bf[2 * ntp][1], bf[2 * ntp + 1][0], bf[2 * ntp + 1][1],
                          Bc + (ks * 16 + lane15) * B_STRIDE + warp_n + ntp * 16 + lhalf * 8);
            #pragma unroll
            for (int mt = 0; mt < 4; mt++)
                #pragma unroll
                for (int nt = 0; nt < 4; nt++)
                    mma_f16(acc[mt][nt], af[mt][0], af[mt][1], af[mt][2], af[mt][3],
                            bf[nt][0], bf[nt][1]);
        }

        // ---- stash next tile ----
        if (kt + 1 < nk) {
            #pragma unroll
            for (int t = 0; t < 4; t++) {
                int r = ar + t * 32;
                uint2 u = make_uint2(pack_h2(av[t].x, av[t].y), pack_h2(av[t].z, av[t].w));
                *reinterpret_cast<uint2*>(An + r * A_STRIDE + ac * 4) = u;
            }
            #pragma unroll
            for (int t = 0; t < 4; t++) {
                int r = br + t * 8;
                uint2 u = make_uint2(pack_h2(bv[t].x, bv[t].y), pack_h2(bv[t].z, bv[t].w));
                *reinterpret_cast<uint2*>(Bn + r * B_STRIDE + bc * 4) = u;
            }
        }
        __syncthreads();
    }

    // --- Epilogue ---
    const int rowbase = by * 128 + warp_m;
    const int colbase = bx * 128 + warp_n;

    #pragma unroll
    for (int mt = 0; mt < 4; mt++) {
        #pragma unroll
        for (int nt = 0; nt < 4; nt++) {
            int c = colbase + nt * 8 + tig * 2;
            float bx_ = bias[c], by_ = bias[c + 1];
            #pragma unroll
            for (int half = 0; half < 2; half++) {
                int r = rowbase + mt * 16 + g + half * 8;
                float v0 = acc[mt][nt][half * 2 + 0] + bx_;
                float v1 = acc[mt][nt][half * 2 + 1] + by_;
                if (GELU) { v0 = gelu_exact(v0); v1 = gelu_exact(v1); }
                if (RES) {
                    float2 rr = *reinterpret_cast<const float2*>(res + (size_t)r * N + c);
                    v0 += rr.x; v1 += rr.y;
                }
                float2 ov = make_float2(v0, v1);
                if (QKV) {
                    int b = r >> 11;
                    int n = r & 2047;
                    int h = c >> 6;
                    int d = c & 63;
                    *reinterpret_cast<float2*>(
                        C + ((size_t)((b * NHEAD + h) * NSEQ + n)) * DHEAD + d) = ov;
                } else {
                    *reinterpret_cast<float2*>(C + (size_t)r * N + c) = ov;
                }
            }
        }
    }
}

template <bool GELU, bool RES, bool QKV>
__global__ void __launch_bounds__(256) hgemm(
    const float* __restrict__ A, const float* __restrict__ B,
    const float* __restrict__ bias, const float* __restrict__ res,
    float* __restrict__ C, int M, int N, int K)
{
    __shared__ __half Ash[2 * A_TILE];
    __shared__ __half Bsh[2 * B_TILE];
    gemm_body<GELU, RES, QKV>(A, B, bias, res, C, M, N, K,
                              Ash, Bsh, blockIdx.x, blockIdx.y);
}

// Fused Q/K/V projection: gridDim.z = 3 selects which weight/bias/output.
__global__ void __launch_bounds__(256) qkv_gemm(
    const float* __restrict__ A,
    const float* __restrict__ W0, const float* __restrict__ W1, const float* __restrict__ W2,
    const float* __restrict__ b0, const float* __restrict__ b1, const float* __restrict__ b2,
    float* __restrict__ C0, float* __restrict__ C1, float* __restrict__ C2)
{
    __shared__ __half Ash[2 * A_TILE];
    __shared__ __half Bsh[2 * B_TILE];
    const float* B    = (blockIdx.z == 0) ? W0 : (blockIdx.z == 1) ? W1 : W2;
    const float* bias = (blockIdx.z == 0) ? b0 : (blockIdx.z == 1) ? b1 : b2;
    float*       C    = (blockIdx.z == 0) ? C0 : (blockIdx.z == 1) ? C1 : C2;
    gemm_body<false, false, true>(A, B, bias, nullptr, C, TOK, FDIM, FDIM,
                                  Ash, Bsh, blockIdx.x, blockIdx.y);
}

// ---------------------------------------------------------------------------
// Tensor-core flash attention (tf32), off-by-one softmax + per-head slimming.
// q/k/v layout: [b][h][n][dh]. out: [token][FDIM].
// Block: 128 threads (4 warps); q-tile 64 rows (16/warp); k-tiles of 64 keys.
// ---------------------------------------------------------------------------
#define KS_S 68

__global__ void __launch_bounds__(128) attn_mma(
    const float* __restrict__ q, const float* __restrict__ k,
    const float* __restrict__ v, const float* __restrict__ slim,
    float* __restrict__ out)
{
    __shared__ uint32_t Ks[64 * KS_S];
    __shared__ uint32_t Vs[64 * KS_S];

    const int bh = blockIdx.x;          // 0..31
    const int b  = bh >> 4;
    const int h  = bh & 15;
    const int qbase = blockIdx.y * 64;

    const int tid  = threadIdx.x;
    const int w    = tid >> 5;
    const int lane = tid & 31;
    const int g    = lane >> 2;         // 0..7
    const int tig  = lane & 3;          // 0..3
    const bool odd = tig & 1;

    // ---- stage Q (scaled by 1/8, tf32) through Ks, extract A-fragments ----
    const float4* Qg = reinterpret_cast<const float4*>(
        q + ((size_t)bh * NSEQ + qbase) * DHEAD);
    #pragma unroll
    for (int i = 0; i < 8; i++) {
        int idx = tid + i * 128;        // 0..1023
        int r = idx >> 4, c4 = idx & 15;
        float4 t = Qg[r * 16 + c4];
        Ks[r * KS_S + c4 * 4 + 0] = f2tf32(t.x * 0.125f);
        Ks[r * KS_S + c4 * 4 + 1] = f2tf32(t.y * 0.125f);
        Ks[r * KS_S + c4 * 4 + 2] = f2tf32(t.z * 0.125f);
        Ks[r * KS_S + c4 * 4 + 3] = f2tf32(t.w * 0.125f);
    }
    __syncthreads();

    uint32_t qa[8][4];
    {
        int row0 = w * 16 + g;
        #pragma unroll
        for (int ks = 0; ks < 8; ks++) {
            qa[ks][0] = Ks[ row0      * KS_S + ks * 8 + tig];
            qa[ks][1] = Ks[(row0 + 8) * KS_S + ks * 8 + tig];
            qa[ks][2] = Ks[ row0      * KS_S + ks * 8 + tig + 4];
            qa[ks][3] = Ks[(row0 + 8) * KS_S + ks * 8 + tig + 4];
        }
    }

    float oacc[8][4];
    #pragma unroll
    for (int nt = 0; nt < 8; nt++)
        #pragma unroll
        for (int r = 0; r < 4; r++) oacc[nt][r] = 0.f;
    float m0 = -1e30f, m1 = -1e30f, l0 = 0.f, l1 = 0.f;

    const float4* Kg = reinterpret_cast<const float4*>(k + (size_t)bh * NSEQ * DHEAD);
    const float4* Vg = reinterpret_cast<const float4*>(v + (size_t)bh * NSEQ * DHEAD);

    for (int kt = 0; kt < NSEQ / 64; kt++) {
        __syncthreads();   // previous tile fully consumed (also guards Q frags, iter 0)
        #pragma unroll
        for (int i = 0; i < 8; i++) {
            int idx = tid + i * 128;
            int r = idx >> 4, c4 = idx & 15;
            float4 tk = Kg[(kt * 64 + r) * 16 + c4];
            Ks[r * KS_S + c4 * 4 + 0] = f2tf32(tk.x);
            Ks[r * KS_S + c4 * 4 + 1] = f2tf32(tk.y);
            Ks[r * KS_S + c4 * 4 + 2] = f2tf32(tk.z);
            Ks[r * KS_S + c4 * 4 + 3] = f2tf32(tk.w);
            float4 tv = Vg[(kt * 64 + r) * 16 + c4];
            Vs[r * KS_S + c4 * 4 + 0] = f2tf32(tv.x);
            Vs[r * KS_S + c4 * 4 + 1] = f2tf32(tv.y);
            Vs[r * KS_S + c4 * 4 + 2] = f2tf32(tv.z);
            Vs[r * KS_S + c4 * 4 + 3] = f2tf32(tv.w);
        }
        __syncthreads();

        // ---- S = Q K^T : 16(q) x 64(keys) per warp ----
        float sacc[8][4];
        #pragma unroll
        for (int nt = 0; nt < 8; nt++)
            #pragma unroll
            for (int r = 0; r < 4; r++) sacc[nt][r] = 0.f;

        #pragma unroll
        for (int nt = 0; nt < 8; nt++) {
            #pragma unroll
            for (int ks = 0; ks < 8; ks++) {
                uint32_t kb0 = Ks[(nt * 8 + g) * KS_S + ks * 8 + tig];
                uint32_t kb1 = Ks[(nt * 8 + g) * KS_S + ks * 8 + tig + 4];
                mma_tf32(sacc[nt], qa[ks][0], qa[ks][1], qa[ks][2], qa[ks][3], kb0, kb1);
            }
        }

        // ---- online off-by-one softmax on the C fragments ----
        float tm0 = -1e30f, tm1 = -1e30f;
        #pragma unroll
        for (int nt = 0; nt < 8; nt++) {
            tm0 = fmaxf(tm0, fmaxf(sacc[nt][0], sacc[nt][1]));
            tm1 = fmaxf(tm1, fmaxf(sacc[nt][2], sacc[nt][3]));
        }
        tm0 = fmaxf(tm0, __shfl_xor_sync(0xffffffffu, tm0, 1));
        tm0 = fmaxf(tm0, __shfl_xor_sync(0xffffffffu, tm0, 2));
        tm1 = fmaxf(tm1, __shfl_xor_sync(0xffffffffu, tm1, 1));
        tm1 = fmaxf(tm1, __shfl_xor_sync(0xffffffffu, tm1, 2));

        float nm0 = fmaxf(m0, tm0), nm1 = fmaxf(m1, tm1);
        float f0 = __expf(m0 - nm0), f1 = __expf(m1 - nm1);
        m0 = nm0; m1 = nm1;

        uint32_t pc[8][4];
        float ps0 = 0.f, ps1 = 0.f;
        #pragma unroll
        for (int nt = 0; nt < 8; nt++) {
            float p0 = __expf(sacc[nt][0] - m0);
            float p1 = __expf(sacc[nt][1] - m0);
            float p2 = __expf(sacc[nt][2] - m1);
            float p3 = __expf(sacc[nt][3] - m1);
            ps0 += p0 + p1; ps1 += p2 + p3;
            pc[nt][0] = f2tf32(p0); pc[nt][1] = f2tf32(p1);
            pc[nt][2] = f2tf32(p2); pc[nt][3] = f2tf32(p3);
        }
        ps0 += __shfl_xor_sync(0xffffffffu, ps0, 1);
        ps0 += __shfl_xor_sync(0xffffffffu, ps0, 2);
        ps1 += __shfl_xor_sync(0xffffffffu, ps1, 1);
        ps1 += __shfl_xor_sync(0xffffffffu, ps1, 2);
        l0 = l0 * f0 + ps0;
        l1 = l1 * f1 + ps1;

        #pragma unroll
        for (int nt = 0; nt < 8; nt++) {
            oacc[nt][0] *= f0; oacc[nt][1] *= f0;
            oacc[nt][2] *= f1; oacc[nt][3] *= f1;
        }

        // ---- O += P V : rearrange P C-frag -> A-frag (quad shuffles), mma ----
        const int srcA = (lane & ~3) | (tig >> 1);
        const int srcB = srcA + 2;
        #pragma unroll
        for (int ks = 0; ks < 8; ks++) {
            uint32_t v0a = __shfl_sync(0xffffffffu, pc[ks][0], srcA);
            uint32_t v1a = __shfl_sync(0xffffffffu, pc[ks][1], srcA);
            uint32_t v2a = __shfl_sync(0xffffffffu, pc[ks][2], srcA);
            uint32_t v3a = __shfl_sync(0xffffffffu, pc[ks][3], srcA);
            uint32_t v0b = __shfl_sync(0xffffffffu, pc[ks][0], srcB);
            uint32_t v1b = __shfl_sync(0xffffffffu, pc[ks][1], srcB);
            uint32_t v2b = __shfl_sync(0xffffffffu, pc[ks][2], srcB);
            uint32_t v3b = __shfl_sync(0xffffffffu, pc[ks][3], srcB);
            uint32_t pa0 = odd ? v1a : v0a;   // row g,   key ks*8+tig
            uint32_t pa1 = odd ? v3a : v2a;   // row g+8, key ks*8+tig
            uint32_t pa2 = odd ? v1b : v0b;   // row g,   key ks*8+tig+4
            uint32_t pa3 = odd ? v3b : v2b;   // row g+8, key ks*8+tig+4
            #pragma unroll
            for (int nt = 0; nt < 8; nt++) {
                uint32_t vb0 = Vs[(ks * 8 + tig)     * KS_S + nt * 8 + g];
                uint32_t vb1 = Vs[(ks * 8 + tig + 4) * KS_S + nt * 8 + g];
                mma_tf32(oacc[nt], pa0, pa1, pa2, pa3, vb0, vb1);
            }
        }
    }

    // ---- write O with 1/(1+l) and slim ----
    float sl = slim[h];
    float inv0 = sl / (1.0f + l0);
    float inv1 = sl / (1.0f + l1);
    int q0 = qbase + w * 16 + g;
    float* ob0 = out + ((size_t)(b * NSEQ + q0))     * FDIM + h * DHEAD;
    float* ob1 = out + ((size_t)(b * NSEQ + q0 + 8)) * FDIM + h * DHEAD;
    #pragma unroll
    for (int nt = 0; nt < 8; nt++) {
        int d = nt * 8 + tig * 2;
        *reinterpret_cast<float2*>(ob0 + d) =
            make_float2(oacc[nt][0] * inv0, oacc[nt][1] * inv0);
        *reinterpret_cast<float2*>(ob1 + d) =
            make_float2(oacc[nt][2] * inv1, oacc[nt][3] * inv1);
    }
}

// ---------------------------------------------------------------------------
// Launch
// ---------------------------------------------------------------------------
extern "C" void kernel_launch(void* const* d_in, const int* in_sizes, int n_in,
                              void* d_out, int out_size)
{
    const float* x    = (const float*)d_in[0];
    const float* ln1g = (const float*)d_in[1];
    const float* ln1b = (const float*)d_in[2];
    const float* Wq   = (const float*)d_in[3];
    const float* bq   = (const float*)d_in[4];
    const float* Wk   = (const float*)d_in[5];
    const float* bk   = (const float*)d_in[6];
    const float* Wv   = (const float*)d_in[7];
    const float* bv   = (const float*)d_in[8];
    const float* Wo   = (const float*)d_in[9];
    const float* bo   = (const float*)d_in[10];
    const float* slim = (const float*)d_in[11];
    const float* ln2g = (const float*)d_in[12];
    const float* ln2b = (const float*)d_in[13];
    const float* W1   = (const float*)d_in[14];
    const float* b1   = (const float*)d_in[15];
    const float* W2   = (const float*)d_in[16];
    const float* b2   = (const float*)d_in[17];
    float* out = (float*)d_out;

    float *ph, *pq, *pk, *pv, *pa, *po, *ph2, *pm1;
    cudaGetSymbolAddress((void**)&ph,  g_h);
    cudaGetSymbolAddress((void**)&pq,  g_q);
    cudaGetSymbolAddress((void**)&pk,  g_k);
    cudaGetSymbolAddress((void**)&pv,  g_v);
    cudaGetSymbolAddress((void**)&pa,  g_attn);
    cudaGetSymbolAddress((void**)&po,  g_out);
    cudaGetSymbolAddress((void**)&ph2, g_h2);
    cudaGetSymbolAddress((void**)&pm1, g_m1);

    dim3 gF(FDIM / 128, TOK / 128);       // (8, 32)
    dim3 gQ(FDIM / 128, TOK / 128, 3);    // fused QKV
    dim3 gM(MLPD / 128, TOK / 128);       // (32, 32)

    // 1. LN1
    ln_kernel<<<TOK, 256>>>(x, ln1g, ln1b, ph);

    // 2. Q/K/V projections (one launch, scatter into [b,h,n,d])
    qkv_gemm<<<gQ, 256>>>(ph, Wq, Wk, Wv, bq, bk, bv, pq, pk, pv);

    // 3. Attention (tensor-core flash, off-by-one softmax + slim)
    attn_mma<<<dim3(2 * NHEAD, NSEQ / 64), 128>>>(pq, pk, pv, slim, pa);

    // 4. Output projection + residual 1
    hgemm<false, true, false><<<gF, 256>>>(pa, Wo, bo, x, po, TOK, FDIM, FDIM);

    // 5. LN2
    ln_kernel<<<TOK, 256>>>(po, ln2g, ln2b, ph2);

    // 6. MLP up + GELU
    hgemm<true, false, false><<<gM, 256>>>(ph2, W1, b1, nullptr, pm1, TOK, MLPD, FDIM);

    // 7. MLP down + GELU + residual 2 -> final output
    hgemm<true, true, false><<<gF, 256>>>(pm1, W2, b2, po, out, TOK, FDIM, MLPD);
}

// round 12
// speedup vs baseline: 11.4584x; 1.4316x over previous
#include <cuda_runtime.h>
#include <cuda_fp16.h>
#include <math.h>
#include <stdint.h>

#define TOK   4096
#define FDIM  1024
#define NHEAD 16
#define DHEAD 64
#define MLPD  4096
#define NSEQ  2048

// ---------------------------------------------------------------------------
// Scratch (device globals: allocation-free per harness rules)
// ---------------------------------------------------------------------------
__device__ float  g_out [TOK * FDIM];   // residual-1 output (fp32: feeds LN2 + res2)
__device__ __half g_hh  [TOK * FDIM];   // LN1 output (fp16)
__device__ __half g_qh  [TOK * FDIM];   // [b][h][n][dh] fp16
__device__ __half g_kh  [TOK * FDIM];
__device__ __half g_vh  [TOK * FDIM];
__device__ __half g_attnh[TOK * FDIM];  // attention out (fp16)
__device__ __half g_h2h [TOK * FDIM];   // LN2 output (fp16)
__device__ __half g_m1h [TOK * MLPD];   // MLP hidden (fp16)
// fp16 weight copies (converted once per launch)
__device__ __half g_wq[FDIM * FDIM];
__device__ __half g_wk[FDIM * FDIM];
__device__ __half g_wv[FDIM * FDIM];
__device__ __half g_wo[FDIM * FDIM];
__device__ __half g_w1[FDIM * MLPD];
__device__ __half g_w2[MLPD * FDIM];

__device__ __forceinline__ float gelu_exact(float x) {
    return 0.5f * x * (1.0f + erff(x * 0.70710678118654752f));
}

__device__ __forceinline__ uint32_t pack_h2(float lo, float hi) {
    __half2 h = __floats2half2_rn(lo, hi);
    return *reinterpret_cast<uint32_t*>(&h);
}

__device__ __forceinline__ void mma_f16(float c[4],
                                        uint32_t a0, uint32_t a1, uint32_t a2, uint32_t a3,
                                        uint32_t b0, uint32_t b1) {
    asm volatile(
        "mma.sync.aligned.m16n8k16.row.col.f32.f16.f16.f32 "
        "{%0,%1,%2,%3}, {%4,%5,%6,%7}, {%8,%9}, {%0,%1,%2,%3};"
        : "+f"(c[0]), "+f"(c[1]), "+f"(c[2]), "+f"(c[3])
        : "r"(a0), "r"(a1), "r"(a2), "r"(a3), "r"(b0), "r"(b1));
}

__device__ __forceinline__ void ldsm_x4(uint32_t& r0, uint32_t& r1,
                                        uint32_t& r2, uint32_t& r3,
                                        const __half* p) {
    uint32_t a = (uint32_t)__cvta_generic_to_shared(p);
    asm volatile("ldmatrix.sync.aligned.m8n8.x4.shared.b16 {%0,%1,%2,%3}, [%4];"
                 : "=r"(r0), "=r"(r1), "=r"(r2), "=r"(r3) : "r"(a));
}

__device__ __forceinline__ void ldsm_x4_t(uint32_t& r0, uint32_t& r1,
                                          uint32_t& r2, uint32_t& r3,
                                          const __half* p) {
    uint32_t a = (uint32_t)__cvta_generic_to_shared(p);
    asm volatile("ldmatrix.sync.aligned.m8n8.x4.trans.shared.b16 {%0,%1,%2,%3}, [%4];"
                 : "=r"(r0), "=r"(r1), "=r"(r2), "=r"(r3) : "r"(a));
}

__device__ __forceinline__ void cp16(__half* smem, const __half* gmem) {
    uint32_t s = (uint32_t)__cvta_generic_to_shared(smem);
    asm volatile("cp.async.cg.shared.global [%0], [%1], 16;" :: "r"(s), "l"(gmem));
}
#define CP_COMMIT() asm volatile("cp.async.commit_group;")
#define CP_WAIT1()  asm volatile("cp.async.wait_group 1;")

// ---------------------------------------------------------------------------
// fp32 -> fp16 conversion (weights), 4 elements/thread
// ---------------------------------------------------------------------------
__global__ void __launch_bounds__(256) f2h_kernel(const float* __restrict__ in,
                                                  __half* __restrict__ out, int n) {
    int i = (blockIdx.x * 256 + threadIdx.x) * 4;
    if (i < n) {
        float4 v = *reinterpret_cast<const float4*>(in + i);
        uint2 u = make_uint2(pack_h2(v.x, v.y), pack_h2(v.z, v.w));
        *reinterpret_cast<uint2*>(out + i) = u;
    }
}

// ---------------------------------------------------------------------------
// LayerNorm: one block per row (1024 floats), 256 threads; fp16 output.
// ---------------------------------------------------------------------------
__global__ void __launch_bounds__(256) ln_kernel(const float* __restrict__ x,
                                                 const float* __restrict__ g,
                                                 const float* __restrict__ b,
                                                 __half* __restrict__ out) {
    int row = blockIdx.x;
    const float4* xr = reinterpret_cast<const float4*>(x + (size_t)row * FDIM);
    float4 v = xr[threadIdx.x];

    float s  = v.x + v.y + v.z + v.w;
    float s2 = v.x * v.x + v.y * v.y + v.z * v.z + v.w * v.w;

    #pragma unroll
    for (int o = 16; o > 0; o >>= 1) {
        s  += __shfl_xor_sync(0xffffffffu, s,  o);
        s2 += __shfl_xor_sync(0xffffffffu, s2, o);
    }
    __shared__ float ss[8], ss2[8];
    int w = threadIdx.x >> 5, lane = threadIdx.x & 31;
    if (lane == 0) { ss[w] = s; ss2[w] = s2; }
    __syncthreads();
    s = 0.f; s2 = 0.f;
    #pragma unroll
    for (int i = 0; i < 8; i++) { s += ss[i]; s2 += ss2[i]; }

    float mu  = s * (1.0f / FDIM);
    float var = s2 * (1.0f / FDIM) - mu * mu;
    float r   = rsqrtf(var + 1e-5f);

    float4 gg = reinterpret_cast<const float4*>(g)[threadIdx.x];
    float4 bb = reinterpret_cast<const float4*>(b)[threadIdx.x];
    float o0 = (v.x - mu) * r * gg.x + bb.x;
    float o1 = (v.y - mu) * r * gg.y + bb.y;
    float o2 = (v.z - mu) * r * gg.z + bb.z;
    float o3 = (v.w - mu) * r * gg.w + bb.w;
    uint2 u = make_uint2(pack_h2(o0, o1), pack_h2(o2, o3));
    *reinterpret_cast<uint2*>(out + (size_t)row * FDIM + threadIdx.x * 4) = u;
}

// ---------------------------------------------------------------------------
// FP16 GEMM (fp32 accumulate), cp.async 3-stage pipeline + ldmatrix.
// C[M,N] = A[M,K] @ B[K,N] + bias.  A,B fp16; epilogue fp32 or fp16 out.
// BM=BN=128, BK=32, 256 threads = 8 warps (2m x 4n), warp tile 64x32.
// ---------------------------------------------------------------------------
#define ASTR 40
#define BSTR 136
#define A_TILE_H (128 * ASTR)
#define B_TILE_H (32 * BSTR)
#define STAGE_H  (A_TILE_H + B_TILE_H)
#define GEMM_SMEM (3 * STAGE_H * 2)     // bytes = 56832

template <bool GELU, bool RES, bool QKV, bool OUTH>
__device__ __forceinline__ void gemm_body(
    const __half* __restrict__ A, const __half* __restrict__ B,
    const float* __restrict__ bias, const float* __restrict__ res,
    void* __restrict__ Cv, int N, int K,
    __half* sm, int bx, int by)
{
    const int tid    = threadIdx.x;
    const int warp   = tid >> 5;
    const int lane   = tid & 31;
    const int g      = lane >> 2;
    const int tig    = lane & 3;
    const int lane15 = lane & 15;
    const int lhalf  = lane >> 4;
    const int warp_m = (warp & 1) * 64;
    const int warp_n = (warp >> 1) * 32;

    const __half* Abase = A + (size_t)by * 128 * K;
    const __half* Bbase = B + bx * 128;

    // cp.async coordinates (16B = 8 halfs per op, 2 ops per array per thread)
    const int a_r0 = tid >> 2, a_c = tid & 3;     // A: rows idx>>2, col16 idx&3
    const int b_c = tid & 15;                      // B: rows idx>>4, col16 idx&15

    float acc[4][4][4];
    #pragma unroll
    for (int mt = 0; mt < 4; mt++)
        #pragma unroll
        for (int nt = 0; nt < 4; nt++)
            #pragma unroll
            for (int r = 0; r < 4; r++) acc[mt][nt][r] = 0.f;

    const int nk = K >> 5;

    auto load_stage = [&](int kt, int s) {
        __half* Asm = sm + s * STAGE_H;
        __half* Bsm = Asm + A_TILE_H;
        const __half* Ag = Abase + kt * 32;
        const __half* Bg = Bbase + (size_t)kt * 32 * N;
        #pragma unroll
        for (int i = 0; i < 2; i++) {
            int r = a_r0 + i * 64;                 // 0..127
            cp16(Asm + r * ASTR + a_c * 8, Ag + (size_t)r * K + a_c * 8);
        }
        #pragma unroll
        for (int i = 0; i < 2; i++) {
            int idx = tid + i * 256;
            int r = idx >> 4;                      // 0..31
            cp16(Bsm + r * BSTR + b_c * 8, Bg + (size_t)r * N + b_c * 8);
        }
    };

    load_stage(0, 0); CP_COMMIT();
    load_stage(1, 1); CP_COMMIT();

    for (int kt = 0; kt < nk; kt++) {
        CP_WAIT1();
        __syncthreads();

        // issue next-next tile into recycled buffer (all warps past prev compute)
        if (kt + 2 < nk) load_stage(kt + 2, (kt + 2) % 3);
        CP_COMMIT();

        const __half* Ac = sm + (kt % 3) * STAGE_H;
        const __half* Bc = Ac + A_TILE_H;

        #pragma unroll
        for (int ks = 0; ks < 2; ks++) {
            uint32_t af[4][4], bf[4][2];
            #pragma unroll
            for (int mt = 0; mt < 4; mt++)
                ldsm_x4(af[mt][0], af[mt][1], af[mt][2], af[mt][3],
                        Ac + (warp_m + mt * 16 + lane15) * ASTR + ks * 16 + lhalf * 8);
            #pragma unroll
            for (int ntp = 0; ntp < 2; ntp++)
                ldsm_x4_t(bf[2 * ntp][0], bf[2 * ntp][1], bf[2 * ntp + 1][0], bf[2 * ntp + 1][1],
                          Bc + (ks * 16 + lane15) * BSTR + warp_n + ntp * 16 + lhalf * 8);
            #pragma unroll
            for (int mt = 0; mt < 4; mt++)
                #pragma unroll
                for (int nt = 0; nt < 4; nt++)
                    mma_f16(acc[mt][nt], af[mt][0], af[mt][1], af[mt][2], af[mt][3],
                            bf[nt][0], bf[nt][1]);
        }
        __syncthreads();
    }

    // --- Epilogue ---
    const int rowbase = by * 128 + warp_m;
    const int colbase = bx * 128 + warp_n;

    #pragma unroll
    for (int mt = 0; mt < 4; mt++) {
        #pragma unroll
        for (int nt = 0; nt < 4; nt++) {
            int c = colbase + nt * 8 + tig * 2;
            float bx_ = bias[c], by_ = bias[c + 1];
            #pragma unroll
            for (int half = 0; half < 2; half++) {
                int r = rowbase + mt * 16 + g + half * 8;
                float v0 = acc[mt][nt][half * 2 + 0] + bx_;
                float v1 = acc[mt][nt][half * 2 + 1] + by_;
                if (GELU) { v0 = gelu_exact(v0); v1 = gelu_exact(v1); }
                if (RES) {
                    float2 rr = *reinterpret_cast<const float2*>(res + (size_t)r * N + c);
                    v0 += rr.x; v1 += rr.y;
                }
                size_t off;
                if (QKV) {
                    int b = r >> 11;
                    int n = r & 2047;
                    int h = c >> 6;
                    int d = c & 63;
                    off = ((size_t)((b * NHEAD + h) * NSEQ + n)) * DHEAD + d;
                } else {
                    off = (size_t)r * N + c;
                }
                if (OUTH) {
                    __half2 hv = __floats2half2_rn(v0, v1);
                    *reinterpret_cast<__half2*>((__half*)Cv + off) = hv;
                } else {
                    *reinterpret_cast<float2*>((float*)Cv + off) = make_float2(v0, v1);
                }
            }
        }
    }
}

template <bool GELU, bool RES, bool QKV, bool OUTH>
__global__ void __launch_bounds__(256) hgemm(
    const __half* __restrict__ A, const __half* __restrict__ B,
    const float* __restrict__ bias, const float* __restrict__ res,
    void* __restrict__ C, int N, int K)
{
    extern __shared__ __half sm[];
    gemm_body<GELU, RES, QKV, OUTH>(A, B, bias, res, C, N, K, sm, blockIdx.x, blockIdx.y);
}

// Fused Q/K/V projection: gridDim.z selects weight/bias/output.
__global__ void __launch_bounds__(256) qkv_gemm(
    const __half* __restrict__ A,
    const __half* __restrict__ W0, const __half* __restrict__ W1, const __half* __restrict__ W2,
    const float* __restrict__ b0, const float* __restrict__ b1, const float* __restrict__ b2,
    __half* __restrict__ C0, __half* __restrict__ C1, __half* __restrict__ C2)
{
    extern __shared__ __half sm[];
    const __half* B    = (blockIdx.z == 0) ? W0 : (blockIdx.z == 1) ? W1 : W2;
    const float* bias  = (blockIdx.z == 0) ? b0 : (blockIdx.z == 1) ? b1 : b2;
    __half*      C     = (blockIdx.z == 0) ? C0 : (blockIdx.z == 1) ? C1 : C2;
    gemm_body<false, false, true, true>(A, B, bias, nullptr, C, FDIM, FDIM,
                                        sm, blockIdx.x, blockIdx.y);
}

// ---------------------------------------------------------------------------
// FP16 tensor-core flash attention, off-by-one softmax + per-head slimming.
// q/k/v fp16 [b][h][n][dh]; out fp16 [token][FDIM].
// 4 warps, 64 q rows/block (16/warp), k-tiles of 64 keys.
// S = Q K^T (mma k16; K rows are B-col-major -> plain ldmatrix).
// P: S C-frag pairs pack directly into PV A-frags (no shuffles).
// Scale 1/8 folded into exp arguments.
// ---------------------------------------------------------------------------
#define QSTR 72

__global__ void __launch_bounds__(128) attn_h(
    const __half* __restrict__ q, const __half* __restrict__ k,
    const __half* __restrict__ v, const float* __restrict__ slim,
    __half* __restrict__ out)
{
    __shared__ __half Ks[64 * QSTR];
    __shared__ __half Vs[64 * QSTR];

    const int bh = blockIdx.x;          // 0..31
    const int b  = bh >> 4;
    const int h  = bh & 15;
    const int qbase = blockIdx.y * 64;

    const int tid    = threadIdx.x;
    const int w      = tid >> 5;
    const int lane   = tid & 31;
    const int g      = lane >> 2;
    const int tig    = lane & 3;
    const int lane15 = lane & 15;
    const int lhalf  = lane >> 4;

    // ---- stage Q through Ks, extract A-fragments (held all loop) ----
    const uint4* Qg = reinterpret_cast<const uint4*>(
        q + ((size_t)bh * NSEQ + qbase) * DHEAD);
    #pragma unroll
    for (int i = 0; i < 4; i++) {
        int idx = tid + i * 128;        // 0..511 chunks of 8 halfs
        int r = idx >> 3, c = idx & 7;
        *reinterpret_cast<uint4*>(Ks + r * QSTR + c * 8) = Qg[r * 8 + c];
    }
    __syncthreads();

    uint32_t qa[4][4];
    #pragma unroll
    for (int ks = 0; ks < 4; ks++)
        ldsm_x4(qa[ks][0], qa[ks][1], qa[ks][2], qa[ks][3],
                Ks + (w * 16 + lane15) * QSTR + ks * 16 + lhalf * 8);

    float oacc[8][4];
    #pragma unroll
    for (int nt = 0; nt < 8; nt++)
        #pragma unroll
        for (int r = 0; r < 4; r++) oacc[nt][r] = 0.f;
    float m0 = -1e30f, m1 = -1e30f, l0 = 0.f, l1 = 0.f;

    const uint4* Kg = reinterpret_cast<const uint4*>(k + (size_t)bh * NSEQ * DHEAD);
    const uint4* Vg = reinterpret_cast<const uint4*>(v + (size_t)bh * NSEQ * DHEAD);

    for (int kt = 0; kt < NSEQ / 64; kt++) {
        __syncthreads();
        #pragma unroll
        for (int i = 0; i < 4; i++) {
            int idx = tid + i * 128;
            int r = idx >> 3, c = idx & 7;
            *reinterpret_cast<uint4*>(Ks + r * QSTR + c * 8) = Kg[(kt * 64 + r) * 8 + c];
            *reinterpret_cast<uint4*>(Vs + r * QSTR + c * 8) = Vg[(kt * 64 + r) * 8 + c];
        }
        __syncthreads();

        // ---- S = Q K^T ----
        float sacc[8][4];
        #pragma unroll
        for (int nt = 0; nt < 8; nt++)
            #pragma unroll
            for (int r = 0; r < 4; r++) sacc[nt][r] = 0.f;

        #pragma unroll
        for (int ks = 0; ks < 4; ks++) {
            uint32_t kb[8][2];
            #pragma unroll
            for (int ntp = 0; ntp < 4; ntp++) {
                int row = ntp * 16 + ((lane & 16) >> 1) + (lane & 7);
                int kof = ks * 16 + (lane & 8);
                ldsm_x4(kb[2 * ntp][0], kb[2 * ntp][1], kb[2 * ntp + 1][0], kb[2 * ntp + 1][1],
                        Ks + row * QSTR + kof);
            }
            #pragma unroll
            for (int nt = 0; nt < 8; nt++)
                mma_f16(sacc[nt], qa[ks][0], qa[ks][1], qa[ks][2], qa[ks][3],
                        kb[nt][0], kb[nt][1]);
        }

        // ---- online off-by-one softmax (scale 1/8 in exp args) ----
        float tm0 = -1e30f, tm1 = -1e30f;
        #pragma unroll
        for (int nt = 0; nt < 8; nt++) {
            tm0 = fmaxf(tm0, fmaxf(sacc[nt][0], sacc[nt][1]));
            tm1 = fmaxf(tm1, fmaxf(sacc[nt][2], sacc[nt][3]));
        }
        tm0 = fmaxf(tm0, __shfl_xor_sync(0xffffffffu, tm0, 1));
        tm0 = fmaxf(tm0, __shfl_xor_sync(0xffffffffu, tm0, 2));
        tm1 = fmaxf(tm1, __shfl_xor_sync(0xffffffffu, tm1, 1));
        tm1 = fmaxf(tm1, __shfl_xor_sync(0xffffffffu, tm1, 2));

        float nm0 = fmaxf(m0, tm0), nm1 = fmaxf(m1, tm1);
        float f0 = __expf((m0 - nm0) * 0.125f), f1 = __expf((m1 - nm1) * 0.125f);
        m0 = nm0; m1 = nm1;

        uint32_t pch[8][2];
        float ps0 = 0.f, ps1 = 0.f;
        #pragma unroll
        for (int nt = 0; nt < 8; nt++) {
            float p0 = __expf((sacc[nt][0] - m0) * 0.125f);
            float p1 = __expf((sacc[nt][1] - m0) * 0.125f);
            float p2 = __expf((sacc[nt][2] - m1) * 0.125f);
            float p3 = __expf((sacc[nt][3] - m1) * 0.125f);
            ps0 += p0 + p1; ps1 += p2 + p3;
            pch[nt][0] = pack_h2(p0, p1);    // (row g,   keys 2tig,2tig+1)
            pch[nt][1] = pack_h2(p2, p3);    // (row g+8, same keys)
        }
        ps0 += __shfl_xor_sync(0xffffffffu, ps0, 1);
        ps0 += __shfl_xor_sync(0xffffffffu, ps0, 2);
        ps1 += __shfl_xor_sync(0xffffffffu, ps1, 1);
        ps1 += __shfl_xor_sync(0xffffffffu, ps1, 2);
        l0 = l0 * f0 + ps0;
        l1 = l1 * f1 + ps1;

        #pragma unroll
        for (int nt = 0; nt < 8; nt++) {
            oacc[nt][0] *= f0; oacc[nt][1] *= f0;
            oacc[nt][2] *= f1; oacc[nt][3] *= f1;
        }

        // ---- O += P V : S C-frags ARE PV A-frags (half2-packed), no shuffles ----
        #pragma unroll
        for (int kb2 = 0; kb2 < 4; kb2++) {
            uint32_t pa0 = pch[2 * kb2][0];
            uint32_t pa1 = pch[2 * kb2][1];
            uint32_t pa2 = pch[2 * kb2 + 1][0];
            uint32_t pa3 = pch[2 * kb2 + 1][1];
            uint32_t vb[8][2];
            #pragma unroll
            for (int ntp = 0; ntp < 4; ntp++)
                ldsm_x4_t(vb[2 * ntp][0], vb[2 * ntp][1], vb[2 * ntp + 1][0], vb[2 * ntp + 1][1],
                          Vs + (kb2 * 16 + lane15) * QSTR + ntp * 16 + lhalf * 8);
            #pragma unroll
            for (int nt = 0; nt < 8; nt++)
                mma_f16(oacc[nt], pa0, pa1, pa2, pa3, vb[nt][0], vb[nt][1]);
        }
    }

    // ---- write O (fp16) with 1/(1+l) and slim ----
    float sl = slim[h];
    float inv0 = sl / (1.0f + l0);
    float inv1 = sl / (1.0f + l1);
    int q0 = qbase + w * 16 + g;
    __half* ob0 = out + ((size_t)(b * NSEQ + q0))     * FDIM + h * DHEAD;
    __half* ob1 = out + ((size_t)(b * NSEQ + q0 + 8)) * FDIM + h * DHEAD;
    #pragma unroll
    for (int nt = 0; nt < 8; nt++) {
        int d = nt * 8 + tig * 2;
        *reinterpret_cast<__half2*>(ob0 + d) =
            __floats2half2_rn(oacc[nt][0] * inv0, oacc[nt][1] * inv0);
        *reinterpret_cast<__half2*>(ob1 + d) =
            __floats2half2_rn(oacc[nt][2] * inv1, oacc[nt][3] * inv1);
    }
}

// ---------------------------------------------------------------------------
// Launch
// ---------------------------------------------------------------------------
extern "C" void kernel_launch(void* const* d_in, const int* in_sizes, int n_in,
                              void* d_out, int out_size)
{
    const float* x    = (const float*)d_in[0];
    const float* ln1g = (const float*)d_in[1];
    const float* ln1b = (const float*)d_in[2];
    const float* Wq   = (const float*)d_in[3];
    const float* bq   = (const float*)d_in[4];
    const float* Wk   = (const float*)d_in[5];
    const float* bk   = (const float*)d_in[6];
    const float* Wv   = (const float*)d_in[7];
    const float* bv   = (const float*)d_in[8];
    const float* Wo   = (const float*)d_in[9];
    const float* bo   = (const float*)d_in[10];
    const float* slim = (const float*)d_in[11];
    const float* ln2g = (const float*)d_in[12];
    const float* ln2b = (const float*)d_in[13];
    const float* W1   = (const float*)d_in[14];
    const float* b1   = (const float*)d_in[15];
    const float* W2   = (const float*)d_in[16];
    const float* b2   = (const float*)d_in[17];
    float* out = (float*)d_out;

    float* pout;
    __half *phh, *pqh, *pkh, *pvh, *pah, *ph2, *pm1;
    __half *pwq, *pwk, *pwv, *pwo, *pw1, *pw2;
    cudaGetSymbolAddress((void**)&pout, g_out);
    cudaGetSymbolAddress((void**)&phh,  g_hh);
    cudaGetSymbolAddress((void**)&pqh,  g_qh);
    cudaGetSymbolAddress((void**)&pkh,  g_kh);
    cudaGetSymbolAddress((void**)&pvh,  g_vh);
    cudaGetSymbolAddress((void**)&pah,  g_attnh);
    cudaGetSymbolAddress((void**)&ph2,  g_h2h);
    cudaGetSymbolAddress((void**)&pm1,  g_m1h);
    cudaGetSymbolAddress((void**)&pwq,  g_wq);
    cudaGetSymbolAddress((void**)&pwk,  g_wk);
    cudaGetSymbolAddress((void**)&pwv,  g_wv);
    cudaGetSymbolAddress((void**)&pwo,  g_wo);
    cudaGetSymbolAddress((void**)&pw1,  g_w1);
    cudaGetSymbolAddress((void**)&pw2,  g_w2);

    cudaFuncSetAttribute(qkv_gemm, cudaFuncAttributeMaxDynamicSharedMemorySize, GEMM_SMEM);
    cudaFuncSetAttribute(hgemm<false, true, false, false>,
                         cudaFuncAttributeMaxDynamicSharedMemorySize, GEMM_SMEM);
    cudaFuncSetAttribute(hgemm<true, false, false, true>,
                         cudaFuncAttributeMaxDynamicSharedMemorySize, GEMM_SMEM);
    cudaFuncSetAttribute(hgemm<true, true, false, false>,
                         cudaFuncAttributeMaxDynamicSharedMemorySize, GEMM_SMEM);

    // 0. convert weights to fp16
    f2h_kernel<<<FDIM * FDIM / 1024, 256>>>(Wq, pwq, FDIM * FDIM);
    f2h_kernel<<<FDIM * FDIM / 1024, 256>>>(Wk, pwk, FDIM * FDIM);
    f2h_kernel<<<FDIM * FDIM / 1024, 256>>>(Wv, pwv, FDIM * FDIM);
    f2h_kernel<<<FDIM * FDIM / 1024, 256>>>(Wo, pwo, FDIM * FDIM);
    f2h_kernel<<<FDIM * MLPD / 1024, 256>>>(W1, pw1, FDIM * MLPD);
    f2h_kernel<<<MLPD * FDIM / 1024, 256>>>(W2, pw2, MLPD * FDIM);

    dim3 gF(FDIM / 128, TOK / 128);       // (8, 32)
    dim3 gQ(FDIM / 128, TOK / 128, 3);
    dim3 gM(MLPD / 128, TOK / 128);       // (32, 32)

    // 1. LN1 -> fp16
    ln_kernel<<<TOK, 256>>>(x, ln1g, ln1b, phh);

    // 2. fused QKV projections -> fp16 [b,h,n,d]
    qkv_gemm<<<gQ, 256, GEMM_SMEM>>>(phh, pwq, pwk, pwv, bq, bk, bv, pqh, pkh, pvh);

    // 3. fp16 flash attention -> fp16 [token][F]
    attn_h<<<dim3(2 * NHEAD, NSEQ / 64), 128>>>(pqh, pkh, pvh, slim, pah);

    // 4. output projection + residual 1 -> fp32
    hgemm<false, true, false, false><<<gF, 256, GEMM_SMEM>>>(pah, pwo, bo, x, pout, FDIM, FDIM);

    // 5. LN2 -> fp16
    ln_kernel<<<TOK, 256>>>(pout, ln2g, ln2b, ph2);

    // 6. MLP up + GELU -> fp16
    hgemm<true, false, false, true><<<gM, 256, GEMM_SMEM>>>(ph2, pw1, b1, nullptr, pm1, MLPD, FDIM);

    // 7. MLP down + GELU + residual 2 -> fp32 final
    hgemm<true, true, false, false><<<gF, 256, GEMM_SMEM>>>(pm1, pw2, b2, pout, out, FDIM, MLPD);
}